// round 12
// baseline (speedup 1.0000x reference)
#include <cuda_runtime.h>
#include <cuda_fp16.h>
#include <math.h>
#include <stdint.h>

// ---------------------------------------------------------------------------
// Problem constants
// ---------------------------------------------------------------------------
#define BATCH 8192
#define SEQ   16
#define DIM   128
#define MTOT  (BATCH * SEQ)        // 131072 rows
#define HID   1024
#define GCN   40
#define NUMF  103
#define EPSV  1e-5f

// Weight-tile store: each "slot" = one 128(N)x64(K) fp16 tile,
// SW128-swizzled 128B rows — ldmatrix-ready. 8192 fp16 = 16KB.
#define SLOT_ELE    8192
#define SLOTS_TOTAL 80               // 40 per layer x 2 layers
// per-layer map: Wq:0-1 Wk:2-3 Wv:4-5 Wo:6-7 W1:8+nb*2+kc W2:24+kc

// GEMM tile: M=128, N=128, Kchunk=64, 4 warps (128 thr), 2 CTAs/SM.
// warp tile 64x64. stage = A 16K + B 16K = 32KB, 3-stage ring.
#define KCH   64
#define OA    0u
#define OB    16384u
#define STAGE_B 32768u
#define NSTAGE 3
#define DSMEM_BYTES (1024 + NSTAGE * STAGE_B)   // 99328

// ---------------------------------------------------------------------------
// Scratch (device globals: the sanctioned no-alloc workaround)
// ---------------------------------------------------------------------------
__device__ float g_X[MTOT * DIM];          // xpe / layer output (fp32)
__device__ float g_Kb[MTOT * DIM];         // h (fp32 residual for FFN2-LN)
__device__ float g_Np[BATCH * DIM];
__device__ float g_bnp[2 * 64 * DIM];
__device__ float g_bns[2 * DIM];
__device__ float g_PE[SEQ * DIM];
__device__ __half g_Wt[(size_t)SLOTS_TOTAL * SLOT_ELE];
// fp16 activation planes
__device__ __half g_Xs[(size_t)MTOT * DIM];   // QKV input
__device__ __half g_Cs[(size_t)MTOT * DIM];   // ctx -> Wo input
__device__ __half g_Hs[(size_t)MTOT * DIM];   // h -> FFN1 input
__device__ __half g_Fs[(size_t)MTOT * HID];   // ffn hidden -> FFN2 input
__device__ __half g_Qh[(size_t)MTOT * DIM];   // q
__device__ __half g_Kh[(size_t)MTOT * DIM];   // k
__device__ __half g_Vh[(size_t)MTOT * DIM];   // v

__device__ __forceinline__ float* self32(int s) {
    switch (s) {
        case 0: return g_X;
        case 2: return g_Kb;
    }
    return nullptr;
}
__device__ __forceinline__ __half* selh(int s) {
    switch (s) {
        case 0: return g_Xs;
        case 1: return g_Cs;
        case 2: return g_Hs;
        case 3: return g_Fs;
        case 4: return g_Qh;
        case 5: return g_Kh;
        case 6: return g_Vh;
    }
    return nullptr;
}

__device__ __forceinline__ float warp_red(float v) {
    #pragma unroll
    for (int o = 16; o; o >>= 1) v += __shfl_xor_sync(0xffffffffu, v, o);
    return v;
}

// ---------------------------------------------------------------------------
// PTX helpers (family-target-safe: ldmatrix sm_75+, mma/cp.async sm_80+)
// ---------------------------------------------------------------------------
__device__ __forceinline__ uint32_t smem_u32(const void* p) {
    uint32_t a;
    asm("{ .reg .u64 t; cvta.to.shared.u64 t, %1; cvt.u32.u64 %0, t; }"
        : "=r"(a) : "l"(p));
    return a;
}

__device__ __forceinline__ void ldm4(uint32_t* r, uint32_t addr) {
    asm volatile("ldmatrix.sync.aligned.m8n8.x4.shared.b16 {%0,%1,%2,%3}, [%4];"
                 : "=r"(r[0]), "=r"(r[1]), "=r"(r[2]), "=r"(r[3]) : "r"(addr));
}

__device__ __forceinline__ void mma16816h(float* c, const uint32_t* a,
                                          const uint32_t* b) {
    asm volatile(
        "mma.sync.aligned.m16n8k16.row.col.f32.f16.f16.f32 "
        "{%0,%1,%2,%3}, {%4,%5,%6,%7}, {%8,%9}, {%0,%1,%2,%3};"
        : "+f"(c[0]), "+f"(c[1]), "+f"(c[2]), "+f"(c[3])
        : "r"(a[0]), "r"(a[1]), "r"(a[2]), "r"(a[3]), "r"(b[0]), "r"(b[1]));
}

__device__ __forceinline__ void cpa16(uint32_t dst, const void* src) {
    asm volatile("{ .reg .u64 g; cvta.to.global.u64 g, %1; "
                 "cp.async.cg.shared.global [%0], [g], 16; }"
                 :: "r"(dst), "l"(src));
}
__device__ __forceinline__ void cp_commit() {
    asm volatile("cp.async.commit_group;" ::: "memory");
}
__device__ __forceinline__ void cp_wait0() {
    asm volatile("cp.async.wait_group 0;" ::: "memory");
}
__device__ __forceinline__ void cp_wait1() {
    asm volatile("cp.async.wait_group 1;" ::: "memory");
}

// SW128 swizzle for 128-byte rows (conflict-free for ldmatrix)
__device__ __forceinline__ uint32_t sw128(uint32_t off) {
    return off ^ ((off >> 3) & 0x70);
}

// pack two floats -> fp16x2 (RN)
__device__ __forceinline__ uint32_t pack_h2(float a, float b) {
    uint32_t h;
    asm("cvt.rn.f16x2.f32 %0, %1, %2;" : "=r"(h) : "f"(b), "f"(a));
    return h;
}

// ---------------------------------------------------------------------------
// PE init + add (writes fp32 and fp16 planes)
// ---------------------------------------------------------------------------
__global__ void pe_init_kernel() {
    int idx = blockIdx.x * 1024 + threadIdx.x;
    if (idx < SEQ * DIM) {
        int s = idx >> 7, d = idx & 127;
        double e = (double)((d >> 1) * 2) / (double)DIM;
        double p = (double)s / pow(10000.0, e);
        g_PE[idx] = (float)((d & 1) ? cos(p) : sin(p));
    }
}

__global__ void add_pe_kernel(const float* __restrict__ x) {
    size_t i4 = (size_t)blockIdx.x * 256 + threadIdx.x;
    float4 xv = ((const float4*)x)[i4];
    int sd = (int)((i4 * 4) & 2047);
    float4 pv = *(const float4*)(g_PE + sd);
    xv.x += pv.x; xv.y += pv.y; xv.z += pv.z; xv.w += pv.w;
    ((float4*)g_X)[i4] = xv;
    *(uint2*)(&g_Xs[i4 * 4]) =
        make_uint2(pack_h2(xv.x, xv.y), pack_h2(xv.z, xv.w));
}

// ---------------------------------------------------------------------------
// Weight prep: transpose + fp16 + SW128-swizzle into 128x64 tiles.
// ---------------------------------------------------------------------------
__global__ __launch_bounds__(256) void prep_weights_kernel(
    const float* __restrict__ Wq, const float* __restrict__ Wk,
    const float* __restrict__ Wv, const float* __restrict__ Wo,
    const float* __restrict__ W1, const float* __restrict__ W2)
{
    int slot = blockIdx.x;
    int l = slot / 40, s = slot % 40;
    const float* W; int Nmat, nb, kc;
    if (s < 8) {
        int m = s >> 1; kc = s & 1; nb = 0; Nmat = 128;
        const float* mats[4] = {Wq, Wk, Wv, Wo};
        W = mats[m] + (size_t)l * DIM * DIM;
    } else if (s < 24) {
        int t = s - 8; nb = t >> 1; kc = t & 1; Nmat = HID;
        W = W1 + (size_t)l * DIM * HID;
    } else {
        int t = s - 24; nb = 0; kc = t; Nmat = 128;
        W = W2 + (size_t)l * HID * DIM;
    }
    char* tile = (char*)(g_Wt + (size_t)slot * SLOT_ELE);

    #pragma unroll
    for (int it = 0; it < 4; it++) {
        int g = it * 256 + threadIdx.x;    // 16B granule 0..1023
        int n_local = g >> 3;
        int kq = (g & 7) * 8;
        uint4 hi4;
        uint32_t* hp = (uint32_t*)&hi4;
        #pragma unroll
        for (int u = 0; u < 4; u++) {
            float v0 = W[(size_t)(kc * 64 + kq + u * 2 + 0) * Nmat + nb * 128 + n_local];
            float v1 = W[(size_t)(kc * 64 + kq + u * 2 + 1) * Nmat + nb * 128 + n_local];
            hp[u] = pack_h2(v0, v1);
        }
        uint32_t sw = sw128((uint32_t)(n_local * 128 + kq * 2));
        *(uint4*)(tile + sw) = hi4;
    }
}

// ---------------------------------------------------------------------------
// cp.async 3-stage GEMM core. Tile 128x128, 4 warps (128 thr), Kchunk=64.
// warp tile 64x64: wm = wid&1 -> rows, wn = wid>>1 -> cols.
// Single-product plain fp16 (fp32 accum). Per k16: 8 LDSM, 32 HMMA.
// EPI: 0 = bias -> fp16 plane; 1 = bias+relu -> fp16 plane;
//      2 = bias+residual+LN -> fp32 C AND fp16 plane
// ---------------------------------------------------------------------------
template <int EPI>
__device__ __forceinline__ void gemm_cp_core(
    char* dsm_raw,
    const __half* __restrict__ A, int lda,
    const __half* __restrict__ Wslots, int nchunks,
    const float* __restrict__ bias,
    const float* __restrict__ R,
    const float* __restrict__ gam, const float* __restrict__ bet,
    float* __restrict__ C, int ldc,
    __half* __restrict__ Sh, int lds,
    int ncoloff, int rb)
{
    __shared__ float s_sp[128][2];
    __shared__ float s_sq[128][2];

    uint32_t raw_u = smem_u32(dsm_raw);
    uint32_t sbase = (raw_u + 1023) & ~1023u;

    int tid = threadIdx.x;
    int wid = tid >> 5, lane = tid & 31;
    int wm = wid & 1, wn = wid >> 1;

    // ldmatrix lane geometry
    int mt = lane >> 3;
    int rr = lane & 7;
    int row_off = ((mt & 1) << 3) + rr;
    int kk_off = (mt >> 1) << 3;

    // A loader: one row per thread, 8 granules along k
    const __half* a_src = A + (size_t)(rb + tid) * lda;
    const char* bbase = (const char*)Wslots;

    float acc[4][8][4];
    #pragma unroll
    for (int i = 0; i < 4; i++)
        #pragma unroll
        for (int j = 0; j < 8; j++)
            #pragma unroll
            for (int r = 0; r < 4; r++) acc[i][j][r] = 0.f;

    auto issue = [&](int buf, int c) {
        uint32_t st = sbase + buf * STAGE_B;
        // A: 128 rows x 64 halves (128B/row), row = tid
        #pragma unroll
        for (int p = 0; p < 8; p++)
            cpa16(st + OA + sw128((uint32_t)(tid * 128 + p * 16)),
                  a_src + c * KCH + p * 8);
        // B slot: 16KB straight copy (pre-swizzled)
        const char* bs = bbase + (size_t)c * 16384;
        #pragma unroll
        for (int p = 0; p < 8; p++) {
            uint32_t off = (uint32_t)((p * 128 + tid) * 16);
            cpa16(st + OB + off, bs + off);
        }
    };

    issue(0, 0);
    cp_commit();
    if (nchunks > 1) { issue(1, 1); cp_commit(); }

    for (int c = 0; c < nchunks; c++) {
        if (c + 1 < nchunks) cp_wait1(); else cp_wait0();
        __syncthreads();
        if (c + 2 < nchunks) { issue((c + 2) % NSTAGE, c + 2); cp_commit(); }

        uint32_t st = sbase + (c % NSTAGE) * STAGE_B;
        #pragma unroll
        for (int k16 = 0; k16 < 4; k16++) {
            int kbase = k16 * 16 + kk_off;
            // B fragments: 4 ldm4 -> 8 n8-frags
            uint32_t bh[8][2];
            #pragma unroll
            for (int in2 = 0; in2 < 4; in2++) {
                int nrow = wn * 64 + in2 * 16 + row_off;
                uint32_t off = sw128((uint32_t)(nrow * 128 + kbase * 2));
                uint32_t t[4];
                ldm4(t, st + OB + off);
                bh[in2 * 2 + 0][0] = t[0]; bh[in2 * 2 + 0][1] = t[2];
                bh[in2 * 2 + 1][0] = t[1]; bh[in2 * 2 + 1][1] = t[3];
            }
            // A fragments: 4 ldm4
            uint32_t af[4][4];
            #pragma unroll
            for (int im = 0; im < 4; im++) {
                int mrow = wm * 64 + im * 16 + row_off;
                ldm4(af[im], st + OA + sw128((uint32_t)(mrow * 128 + kbase * 2)));
            }
            // 32 MMAs
            #pragma unroll
            for (int im = 0; im < 4; im++)
                #pragma unroll
                for (int in = 0; in < 8; in++)
                    mma16816h(acc[im][in], af[im], bh[in]);
        }
        __syncthreads();
    }

    // ---- epilogue ----
    int r_in = lane >> 2;
    int c_in = (lane & 3) * 2;

    if (EPI == 0 || EPI == 1) {
        #pragma unroll
        for (int im = 0; im < 4; im++) {
            size_t gr0 = (size_t)(rb + wm * 64 + im * 16 + r_in);
            #pragma unroll
            for (int in = 0; in < 8; in++) {
                int cl = wn * 64 + in * 8 + c_in;
                float b0 = bias[cl], b1 = bias[cl + 1];
                float v0 = acc[im][in][0] + b0, v1 = acc[im][in][1] + b1;
                float v2 = acc[im][in][2] + b0, v3 = acc[im][in][3] + b1;
                if (EPI == 1) {
                    v0 = fmaxf(v0, 0.f); v1 = fmaxf(v1, 0.f);
                    v2 = fmaxf(v2, 0.f); v3 = fmaxf(v3, 0.f);
                }
                *(uint32_t*)&Sh[gr0 * lds + ncoloff + cl] = pack_h2(v0, v1);
                *(uint32_t*)&Sh[(gr0 + 8) * lds + ncoloff + cl] = pack_h2(v2, v3);
            }
        }
    } else {
        float sv[4][2] = {}, qv[4][2] = {};
        #pragma unroll
        for (int im = 0; im < 4; im++) {
            size_t gr0 = (size_t)(rb + wm * 64 + im * 16 + r_in);
            #pragma unroll
            for (int in = 0; in < 8; in++) {
                int cl = wn * 64 + in * 8 + c_in;
                float b0 = bias[cl], b1 = bias[cl + 1];
                float2 rv0 = *(const float2*)(R + gr0 * DIM + cl);
                float2 rv1 = *(const float2*)(R + (gr0 + 8) * DIM + cl);
                float v0 = acc[im][in][0] + b0 + rv0.x;
                float v1 = acc[im][in][1] + b1 + rv0.y;
                float v2 = acc[im][in][2] + b0 + rv1.x;
                float v3 = acc[im][in][3] + b1 + rv1.y;
                acc[im][in][0] = v0; acc[im][in][1] = v1;
                acc[im][in][2] = v2; acc[im][in][3] = v3;
                sv[im][0] += v0 + v1; qv[im][0] += v0 * v0 + v1 * v1;
                sv[im][1] += v2 + v3; qv[im][1] += v2 * v2 + v3 * v3;
            }
        }
        #pragma unroll
        for (int im = 0; im < 4; im++)
            #pragma unroll
            for (int h2 = 0; h2 < 2; h2++) {
                float s = sv[im][h2], q = qv[im][h2];
                s += __shfl_xor_sync(0xffffffffu, s, 1);
                s += __shfl_xor_sync(0xffffffffu, s, 2);
                q += __shfl_xor_sync(0xffffffffu, q, 1);
                q += __shfl_xor_sync(0xffffffffu, q, 2);
                if ((lane & 3) == 0) {
                    int rl = wm * 64 + im * 16 + r_in + h2 * 8;
                    s_sp[rl][wn] = s;
                    s_sq[rl][wn] = q;
                }
            }
        __syncthreads();
        float mn[4][2], rs[4][2];
        #pragma unroll
        for (int im = 0; im < 4; im++)
            #pragma unroll
            for (int h2 = 0; h2 < 2; h2++) {
                int rl = wm * 64 + im * 16 + r_in + h2 * 8;
                float s = s_sp[rl][0] + s_sp[rl][1];
                float q = s_sq[rl][0] + s_sq[rl][1];
                float m = s * (1.f / 128.f);
                float var = q * (1.f / 128.f) - m * m;
                mn[im][h2] = m;
                rs[im][h2] = rsqrtf(var + EPSV);
            }
        #pragma unroll
        for (int im = 0; im < 4; im++) {
            size_t gr0 = (size_t)(rb + wm * 64 + im * 16 + r_in);
            #pragma unroll
            for (int in = 0; in < 8; in++) {
                int cl = wn * 64 + in * 8 + c_in;
                float g0 = gam[cl], g1 = gam[cl + 1];
                float e0 = bet[cl], e1 = bet[cl + 1];
                float o0 = (acc[im][in][0] - mn[im][0]) * rs[im][0] * g0 + e0;
                float o1 = (acc[im][in][1] - mn[im][0]) * rs[im][0] * g1 + e1;
                float o2 = (acc[im][in][2] - mn[im][1]) * rs[im][1] * g0 + e0;
                float o3 = (acc[im][in][3] - mn[im][1]) * rs[im][1] * g1 + e1;
                *(float2*)(C + gr0 * ldc + cl) = make_float2(o0, o1);
                *(float2*)(C + (gr0 + 8) * ldc + cl) = make_float2(o2, o3);
                *(uint32_t*)&Sh[gr0 * lds + cl] = pack_h2(o0, o1);
                *(uint32_t*)&Sh[(gr0 + 8) * lds + cl] = pack_h2(o2, o3);
            }
        }
    }
}

// Generic GEMM kernel: blockIdx.x = col block, blockIdx.y = row block (128)
template <int EPI>
__global__ __launch_bounds__(128, 2) void gemm_cp_kernel(
    int absel, int lda, int slotbase, int kchunks,
    const float* __restrict__ bias, int rsel,
    const float* __restrict__ gam, const float* __restrict__ bet,
    int csel, int ldc, int ssel, int lds)
{
    extern __shared__ char dsm[];
    int nb = blockIdx.x;
    int rb = blockIdx.y * 128;
    const __half* Ah = selh(absel);
    __half* Sh = selh(ssel);
    const __half* Ws =
        g_Wt + ((size_t)slotbase + (size_t)nb * kchunks) * SLOT_ELE;
    gemm_cp_core<EPI>(dsm, Ah, lda, Ws, kchunks,
                      bias + nb * 128,
                      rsel >= 0 ? self32(rsel) : nullptr, gam, bet,
                      csel >= 0 ? self32(csel) : nullptr, ldc,
                      Sh, lds, nb * 128, rb);
}

// QKV fused: blockIdx.x selects q/k/v (co-scheduled -> A L2 reuse)
__global__ __launch_bounds__(128, 2) void qkv_cp_kernel(
    int lslot, const float* __restrict__ bq,
    const float* __restrict__ bk, const float* __restrict__ bv)
{
    extern __shared__ char dsm[];
    int which = blockIdx.x;
    int rb = blockIdx.y * 128;
    const __half* Ws = g_Wt + (size_t)(lslot + which * 2) * SLOT_ELE;
    const float* bias = (which == 0) ? bq : (which == 1) ? bk : bv;
    __half* Sh = (which == 0) ? g_Qh : (which == 1) ? g_Kh : g_Vh;
    gemm_cp_core<0>(dsm, g_Xs, DIM, Ws, 2, bias,
                    nullptr, nullptr, nullptr, nullptr, 0,
                    Sh, DIM, 0, rb);
}

// ---------------------------------------------------------------------------
// Attention: one warp per 16x16 unit; fp16 in (g_Qh/g_Kh/g_Vh), fp16 out (g_Cs)
// ---------------------------------------------------------------------------
__global__ __launch_bounds__(256) void attn_kernel() {
    __shared__ float s_q[8][256];
    __shared__ float s_k[8][256];
    __shared__ float s_v[8][256];

    int w = threadIdx.x >> 5, lane = threadIdx.x & 31;
    size_t n = (size_t)blockIdx.x * 8 + w;
    size_t bse = n * 256;

    {
        uint4 qv = *(const uint4*)(g_Qh + bse + lane * 8);
        uint4 kv = *(const uint4*)(g_Kh + bse + lane * 8);
        uint4 vv = *(const uint4*)(g_Vh + bse + lane * 8);
        const uint32_t* qp = (const uint32_t*)&qv;
        const uint32_t* kp = (const uint32_t*)&kv;
        const uint32_t* vp = (const uint32_t*)&vv;
        #pragma unroll
        for (int u = 0; u < 4; u++) {
            float2 f;
            f = __half22float2(*(const __half2*)&qp[u]);
            s_q[w][lane * 8 + u * 2] = f.x; s_q[w][lane * 8 + u * 2 + 1] = f.y;
            f = __half22float2(*(const __half2*)&kp[u]);
            s_k[w][lane * 8 + u * 2] = f.x; s_k[w][lane * 8 + u * 2 + 1] = f.y;
            f = __half22float2(*(const __half2*)&vp[u]);
            s_v[w][lane * 8 + u * 2] = f.x; s_v[w][lane * 8 + u * 2 + 1] = f.y;
        }
    }
    __syncwarp();

    int i = lane >> 1;
    int jb = (lane & 1) * 8;

    float qr[16];
    #pragma unroll
    for (int u = 0; u < 4; u++) {
        float4 t4 = *(const float4*)&s_q[w][i * 16 + u * 4];
        qr[u * 4 + 0] = t4.x; qr[u * 4 + 1] = t4.y;
        qr[u * 4 + 2] = t4.z; qr[u * 4 + 3] = t4.w;
    }

    float sc[8];
    #pragma unroll
    for (int j = 0; j < 8; j++) {
        const float* kr = &s_k[w][(jb + j) * 16];
        float dd = 0.f;
        #pragma unroll
        for (int u = 0; u < 16; u++) dd = fmaf(qr[u], kr[u], dd);
        sc[j] = dd * 0.25f;
    }

    float mx = sc[0];
    #pragma unroll
    for (int j = 1; j < 8; j++) mx = fmaxf(mx, sc[j]);
    mx = fmaxf(mx, __shfl_xor_sync(0xffffffffu, mx, 1));

    float sum = 0.f;
    #pragma unroll
    for (int j = 0; j < 8; j++) { sc[j] = __expf(sc[j] - mx); sum += sc[j]; }
    sum += __shfl_xor_sync(0xffffffffu, sum, 1);
    float inv = 1.f / sum;

    float acc[16] = {};
    #pragma unroll
    for (int j = 0; j < 8; j++) {
        float p = sc[j] * inv;
        const float* vr = &s_v[w][(jb + j) * 16];
        #pragma unroll
        for (int u = 0; u < 16; u++) acc[u] = fmaf(p, vr[u], acc[u]);
    }
    #pragma unroll
    for (int u = 0; u < 16; u++)
        acc[u] += __shfl_xor_sync(0xffffffffu, acc[u], 1);

    int db = (lane & 1) * 8;
    size_t e = bse + i * 16 + db;
    *(uint4*)(&g_Cs[e]) = make_uint4(
        pack_h2(acc[db + 0], acc[db + 1]), pack_h2(acc[db + 2], acc[db + 3]),
        pack_h2(acc[db + 4], acc[db + 5]), pack_h2(acc[db + 6], acc[db + 7]));
}

// ---------------------------------------------------------------------------
// Head
// ---------------------------------------------------------------------------
__global__ __launch_bounds__(128) void numproj_kernel(
    const float* __restrict__ num, const float* __restrict__ Wn,
    const float* __restrict__ bnum)
{
    __shared__ float sn[NUMF];
    int b = blockIdx.x, t = threadIdx.x;
    if (t < NUMF) sn[t] = num[(size_t)b * NUMF + t];
    __syncthreads();
    float acc = bnum[t];
    #pragma unroll 1
    for (int k = 0; k < NUMF; k++)
        acc = fmaf(sn[k], Wn[k * DIM + t], acc);
    g_Np[(size_t)b * DIM + t] = acc;
}

__global__ __launch_bounds__(256) void bn_partial_kernel() {
    int j = blockIdx.x, t = threadIdx.x;
    int col = t & 127, half = t >> 7;
    float s = 0.f, q = 0.f;
    for (int i = 0; i < 64; i++) {
        float v = g_Np[(size_t)(j * 128 + half * 64 + i) * DIM + col];
        s += v; q += v * v;
    }
    __shared__ float ss[256], sq[256];
    ss[t] = s; sq[t] = q;
    __syncthreads();
    if (half == 0) {
        g_bnp[j * DIM + col]            = ss[t] + ss[t + 128];
        g_bnp[64 * DIM + j * DIM + col] = sq[t] + sq[t + 128];
    }
}

__global__ __launch_bounds__(128) void bn_final_kernel(
    const float* __restrict__ gamma, const float* __restrict__ beta)
{
    int c = threadIdx.x;
    float s = 0.f, q = 0.f;
    for (int j = 0; j < 64; j++) {
        s += g_bnp[j * DIM + c];
        q += g_bnp[64 * DIM + j * DIM + c];
    }
    float mu = s * (1.f / 8192.f);
    float var = q * (1.f / 8192.f) - mu * mu;
    float a = gamma[c] * rsqrtf(var + EPSV);
    g_bns[c] = a;
    g_bns[DIM + c] = beta[c] - mu * a;
}

__global__ __launch_bounds__(256) void final_kernel(
    const float* __restrict__ gcn, const float* __restrict__ Wf,
    const float* __restrict__ bf, float* __restrict__ out)
{
    int b = blockIdx.x, t = threadIdx.x;
    const float* xr = g_X + (size_t)b * (SEQ * DIM);
    float acc = 0.f;
    #pragma unroll
    for (int i = 0; i < 8; i++) {
        int idx = t + 256 * i;
        acc = fmaf(xr[idx], Wf[idx], acc);
    }
    if (t < GCN)
        acc = fmaf(gcn[(size_t)b * GCN + t], Wf[SEQ * DIM + t], acc);
    if (t < DIM) {
        float v = g_Np[(size_t)b * DIM + t] * g_bns[t] + g_bns[DIM + t];
        acc = fmaf(v, Wf[SEQ * DIM + GCN + t], acc);
    }
    acc = warp_red(acc);
    __shared__ float red[8];
    if ((t & 31) == 0) red[t >> 5] = acc;
    __syncthreads();
    if (t == 0) {
        float z = red[0] + red[1] + red[2] + red[3]
                + red[4] + red[5] + red[6] + red[7] + bf[0];
        out[b] = 1.f / (1.f + expf(-z));
    }
}

// ---------------------------------------------------------------------------
// Launch
// ---------------------------------------------------------------------------
extern "C" void kernel_launch(void* const* d_in, const int* in_sizes, int n_in,
                              void* d_out, int out_size)
{
    const float* x    = (const float*)d_in[0];
    const float* gcn  = (const float*)d_in[1];
    const float* num  = (const float*)d_in[2];
    const float* Wq   = (const float*)d_in[3];
    const float* bq   = (const float*)d_in[4];
    const float* Wk   = (const float*)d_in[5];
    const float* bk   = (const float*)d_in[6];
    const float* Wv   = (const float*)d_in[7];
    const float* bv   = (const float*)d_in[8];
    const float* Wo   = (const float*)d_in[9];
    const float* bo   = (const float*)d_in[10];
    const float* ln1g = (const float*)d_in[11];
    const float* ln1b = (const float*)d_in[12];
    const float* W1   = (const float*)d_in[13];
    const float* b1   = (const float*)d_in[14];
    const float* W2   = (const float*)d_in[15];
    const float* b2   = (const float*)d_in[16];
    const float* ln2g = (const float*)d_in[17];
    const float* ln2b = (const float*)d_in[18];
    const float* Wn   = (const float*)d_in[19];
    const float* bnum = (const float*)d_in[20];
    const float* bng  = (const float*)d_in[21];
    const float* bnb  = (const float*)d_in[22];
    const float* Wf   = (const float*)d_in[23];
    const float* bf   = (const float*)d_in[24];
    float* out = (float*)d_out;

    cudaFuncSetAttribute(qkv_cp_kernel,
        cudaFuncAttributeMaxDynamicSharedMemorySize, DSMEM_BYTES);
    cudaFuncSetAttribute(gemm_cp_kernel<1>,
        cudaFuncAttributeMaxDynamicSharedMemorySize, DSMEM_BYTES);
    cudaFuncSetAttribute(gemm_cp_kernel<2>,
        cudaFuncAttributeMaxDynamicSharedMemorySize, DSMEM_BYTES);

    pe_init_kernel<<<2, 1024>>>();
    prep_weights_kernel<<<SLOTS_TOTAL, 256>>>(Wq, Wk, Wv, Wo, W1, W2);
    add_pe_kernel<<<16384, 256>>>(x);

    const int RB = MTOT / 128;   // 1024 row blocks
    for (int l = 0; l < 2; l++) {
        int lb = l * 40;
        // QKV: g_Xs -> Qh,Kh,Vh (fp16)
        qkv_cp_kernel<<<dim3(3, RB), 128, DSMEM_BYTES>>>(
            lb, bq + l * DIM, bk + l * DIM, bv + l * DIM);
        // attention: fp16 q,k,v -> ctx fp16 (g_Cs)
        attn_kernel<<<MTOT / 16, 256>>>();
        // h = LN(ctx @ Wo + bo + X): fp32 -> g_Kb, fp16 -> g_Hs
        gemm_cp_kernel<2><<<dim3(1, RB), 128, DSMEM_BYTES>>>(
            1, DIM, lb + 6, 2, bo + l * DIM, 0,
            ln1g + l * DIM, ln1b + l * DIM, 2, DIM, 2, DIM);
        // ffn hidden = relu(h @ W1 + b1): fp16 -> g_Fs
        gemm_cp_kernel<1><<<dim3(8, RB), 128, DSMEM_BYTES>>>(
            2, DIM, lb + 8, 2, b1 + l * HID, -1,
            nullptr, nullptr, -1, 0, 3, HID);
        // out = LN(ffn @ W2 + b2 + h): fp32 -> g_X, fp16 -> g_Xs
        gemm_cp_kernel<2><<<dim3(1, RB), 128, DSMEM_BYTES>>>(
            3, HID, lb + 24, 16, b2 + l * DIM, 2,
            ln2g + l * DIM, ln2b + l * DIM, 0, DIM, 0, DIM);
    }

    numproj_kernel<<<BATCH, 128>>>(num, Wn, bnum);
    bn_partial_kernel<<<64, 256>>>();
    bn_final_kernel<<<1, 128>>>(bng, bnb);
    final_kernel<<<BATCH, 256>>>(gcn, Wf, bf, out);
}

// round 14
// speedup vs baseline: 1.2185x; 1.2185x over previous
#include <cuda_runtime.h>
#include <cuda_fp16.h>
#include <math.h>
#include <stdint.h>

// ---------------------------------------------------------------------------
// Problem constants
// ---------------------------------------------------------------------------
#define BATCH 8192
#define SEQ   16
#define DIM   128
#define MTOT  (BATCH * SEQ)        // 131072 rows
#define HID   1024
#define GCN   40
#define NUMF  103
#define EPSV  1e-5f

// Weight-tile store: each "slot" = one 128(N)x32(K) fp16 tile,
// SW64-swizzled 64B rows — ldmatrix-ready. 4096 fp16 = 8KB.
#define SLOT_ELE    4096
#define SLOTS_TOTAL 160              // 80 per layer x 2 layers
// per-layer map: Wq:0-3 Wk:4-7 Wv:8-11 Wo:12-15 W1:16+nb*4+kc W2:48+kc

// Generic GEMM tile: M=128, N=128, Kchunk=32, 8 warps (256 thr), 2 CTAs/SM.
#define KCH   32
#define OA    0u
#define OB    8192u
#define STAGE_B 16384u
#define NSTAGE 3
#define DSMEM_BYTES (1024 + NSTAGE * STAGE_B)   // 50176

// Fused-FFN smem: h 16KB + Hj 16KB + B-ring 3x8KB = 56KB (+1KB align)
#define FF_STAGE 8192u
#define FF_H  0u
#define FF_HJ 16384u
#define FF_B  32768u
#define DSMEM_FF (1024 + 32768 + 3 * FF_STAGE)   // 58368

// ---------------------------------------------------------------------------
// Scratch (device globals: the sanctioned no-alloc workaround)
// ---------------------------------------------------------------------------
__device__ float g_X[MTOT * DIM];          // xpe / layer output (fp32)
__device__ float g_Kb[MTOT * DIM];         // h (fp32 residual for FFN2-LN)
__device__ float g_Np[BATCH * DIM];
__device__ float g_bnp[2 * 64 * DIM];
__device__ float g_bns[2 * DIM];
__device__ float g_PE[SEQ * DIM];
__device__ __half g_Wt[(size_t)SLOTS_TOTAL * SLOT_ELE];
// fp16 activation planes
__device__ __half g_Xs[(size_t)MTOT * DIM];   // QKV input
__device__ __half g_Cs[(size_t)MTOT * DIM];   // ctx -> Wo input
__device__ __half g_Hs[(size_t)MTOT * DIM];   // h -> FFN input
__device__ __half g_Qh[(size_t)MTOT * DIM];   // q
__device__ __half g_Kh[(size_t)MTOT * DIM];   // k
__device__ __half g_Vh[(size_t)MTOT * DIM];   // v

__device__ __forceinline__ float* self32(int s) {
    switch (s) {
        case 0: return g_X;
        case 2: return g_Kb;
    }
    return nullptr;
}
__device__ __forceinline__ __half* selh(int s) {
    switch (s) {
        case 0: return g_Xs;
        case 1: return g_Cs;
        case 2: return g_Hs;
        case 4: return g_Qh;
        case 5: return g_Kh;
        case 6: return g_Vh;
    }
    return nullptr;
}

__device__ __forceinline__ float warp_red(float v) {
    #pragma unroll
    for (int o = 16; o; o >>= 1) v += __shfl_xor_sync(0xffffffffu, v, o);
    return v;
}

// ---------------------------------------------------------------------------
// PTX helpers (family-target-safe: ldmatrix sm_75+, mma/cp.async sm_80+)
// ---------------------------------------------------------------------------
__device__ __forceinline__ uint32_t smem_u32(const void* p) {
    uint32_t a;
    asm("{ .reg .u64 t; cvta.to.shared.u64 t, %1; cvt.u32.u64 %0, t; }"
        : "=r"(a) : "l"(p));
    return a;
}

__device__ __forceinline__ void ldm4(uint32_t* r, uint32_t addr) {
    asm volatile("ldmatrix.sync.aligned.m8n8.x4.shared.b16 {%0,%1,%2,%3}, [%4];"
                 : "=r"(r[0]), "=r"(r[1]), "=r"(r[2]), "=r"(r[3]) : "r"(addr));
}

__device__ __forceinline__ void mma16816h(float* c, const uint32_t* a,
                                          const uint32_t* b) {
    asm volatile(
        "mma.sync.aligned.m16n8k16.row.col.f32.f16.f16.f32 "
        "{%0,%1,%2,%3}, {%4,%5,%6,%7}, {%8,%9}, {%0,%1,%2,%3};"
        : "+f"(c[0]), "+f"(c[1]), "+f"(c[2]), "+f"(c[3])
        : "r"(a[0]), "r"(a[1]), "r"(a[2]), "r"(a[3]), "r"(b[0]), "r"(b[1]));
}

__device__ __forceinline__ void cpa16(uint32_t dst, const void* src) {
    asm volatile("{ .reg .u64 g; cvta.to.global.u64 g, %1; "
                 "cp.async.cg.shared.global [%0], [g], 16; }"
                 :: "r"(dst), "l"(src));
}
__device__ __forceinline__ void cp_commit() {
    asm volatile("cp.async.commit_group;" ::: "memory");
}
__device__ __forceinline__ void cp_wait0() {
    asm volatile("cp.async.wait_group 0;" ::: "memory");
}
__device__ __forceinline__ void cp_wait1() {
    asm volatile("cp.async.wait_group 1;" ::: "memory");
}

// SW64 swizzle for 64-byte rows
__device__ __forceinline__ uint32_t sw64(uint32_t off) {
    return off ^ ((off >> 3) & 0x30);
}

// pack two floats -> fp16x2 (RN)
__device__ __forceinline__ uint32_t pack_h2(float a, float b) {
    uint32_t h;
    asm("cvt.rn.f16x2.f32 %0, %1, %2;" : "=r"(h) : "f"(b), "f"(a));
    return h;
}

// ---------------------------------------------------------------------------
// PE init + add (writes fp32 and fp16 planes)
// ---------------------------------------------------------------------------
__global__ void pe_init_kernel() {
    int idx = blockIdx.x * 1024 + threadIdx.x;
    if (idx < SEQ * DIM) {
        int s = idx >> 7, d = idx & 127;
        double e = (double)((d >> 1) * 2) / (double)DIM;
        double p = (double)s / pow(10000.0, e);
        g_PE[idx] = (float)((d & 1) ? cos(p) : sin(p));
    }
}

__global__ void add_pe_kernel(const float* __restrict__ x) {
    size_t i4 = (size_t)blockIdx.x * 256 + threadIdx.x;
    float4 xv = ((const float4*)x)[i4];
    int sd = (int)((i4 * 4) & 2047);
    float4 pv = *(const float4*)(g_PE + sd);
    xv.x += pv.x; xv.y += pv.y; xv.z += pv.z; xv.w += pv.w;
    ((float4*)g_X)[i4] = xv;
    *(uint2*)(&g_Xs[i4 * 4]) =
        make_uint2(pack_h2(xv.x, xv.y), pack_h2(xv.z, xv.w));
}

// ---------------------------------------------------------------------------
// Weight prep: transpose + fp16 + SW64-swizzle into 128x32 tiles.
// ---------------------------------------------------------------------------
__global__ __launch_bounds__(256) void prep_weights_kernel(
    const float* __restrict__ Wq, const float* __restrict__ Wk,
    const float* __restrict__ Wv, const float* __restrict__ Wo,
    const float* __restrict__ W1, const float* __restrict__ W2)
{
    int slot = blockIdx.x;
    int l = slot / 80, s = slot % 80;
    const float* W; int Nmat, nb, kc;
    if (s < 16) {
        int m = s >> 2; kc = s & 3; nb = 0; Nmat = 128;
        const float* mats[4] = {Wq, Wk, Wv, Wo};
        W = mats[m] + (size_t)l * DIM * DIM;
    } else if (s < 48) {
        int t = s - 16; nb = t >> 2; kc = t & 3; Nmat = HID;
        W = W1 + (size_t)l * DIM * HID;
    } else {
        int t = s - 48; nb = 0; kc = t; Nmat = 128;
        W = W2 + (size_t)l * HID * DIM;
    }
    char* tile = (char*)(g_Wt + (size_t)slot * SLOT_ELE);

    {
        int g = threadIdx.x;               // 16B granule 0..511 (2 per thread)
        #pragma unroll
        for (int it = 0; it < 2; it++, g += 256) {
            int n_local = g >> 2;
            int kq = (g & 3) * 8;
            uint4 hi4;
            uint32_t* hp = (uint32_t*)&hi4;
            #pragma unroll
            for (int u = 0; u < 4; u++) {
                float v0 = W[(size_t)(kc * 32 + kq + u * 2 + 0) * Nmat + nb * 128 + n_local];
                float v1 = W[(size_t)(kc * 32 + kq + u * 2 + 1) * Nmat + nb * 128 + n_local];
                hp[u] = pack_h2(v0, v1);
            }
            uint32_t sw = sw64((uint32_t)(n_local * 64 + kq * 2));
            *(uint4*)(tile + sw) = hi4;
        }
    }
}

// ---------------------------------------------------------------------------
// cp.async 3-stage GEMM core (R11-proven). Tile 128x128, 8 warps, Kchunk=32.
// warp: wm = wid&1 -> rows wm*64+[0,64); wn = wid>>1 -> cols wn*32+[0,32).
// EPI: 0 = bias -> fp16 plane; 2 = bias+residual+LN -> fp32 C AND fp16 plane
// ---------------------------------------------------------------------------
template <int EPI>
__device__ __forceinline__ void gemm_cp_core(
    char* dsm_raw,
    const __half* __restrict__ A, int lda,
    const __half* __restrict__ Wslots, int nchunks,
    const float* __restrict__ bias,
    const float* __restrict__ R,
    const float* __restrict__ gam, const float* __restrict__ bet,
    float* __restrict__ C, int ldc,
    __half* __restrict__ Sh, int lds,
    int ncoloff, int rb)
{
    __shared__ float s_sp[128][4];
    __shared__ float s_sq[128][4];

    uint32_t raw_u = smem_u32(dsm_raw);
    uint32_t sbase = (raw_u + 1023) & ~1023u;

    int tid = threadIdx.x;
    int wid = tid >> 5, lane = tid & 31;
    int wm = wid & 1, wn = wid >> 1;

    int mt = lane >> 3;
    int rr = lane & 7;
    int row_off = ((mt & 1) << 3) + rr;
    int kk_off = (mt >> 1) << 3;

    uint32_t ag_sw[2];
    const __half* ag_src[2];
    #pragma unroll
    for (int p = 0; p < 2; p++) {
        int g = p * 256 + tid;
        int arow = g >> 2, kq = (g & 3) * 8;
        ag_sw[p] = sw64((uint32_t)(arow * 64 + kq * 2));
        ag_src[p] = A + (size_t)(rb + arow) * lda + kq;
    }
    const char* bbase = (const char*)Wslots;

    float acc[4][4][4];
    #pragma unroll
    for (int i = 0; i < 4; i++)
        #pragma unroll
        for (int j = 0; j < 4; j++)
            #pragma unroll
            for (int r = 0; r < 4; r++) acc[i][j][r] = 0.f;

    auto issue = [&](int buf, int c) {
        uint32_t st = sbase + buf * STAGE_B;
        #pragma unroll
        for (int p = 0; p < 2; p++)
            cpa16(st + OA + ag_sw[p], ag_src[p] + c * KCH);
        const char* bs = bbase + (size_t)c * 8192;
        #pragma unroll
        for (int p = 0; p < 2; p++) {
            uint32_t off = (uint32_t)((p * 256 + tid) * 16);
            cpa16(st + OB + off, bs + off);
        }
    };

    issue(0, 0);
    cp_commit();
    if (nchunks > 1) { issue(1, 1); cp_commit(); }

    for (int c = 0; c < nchunks; c++) {
        if (c + 1 < nchunks) cp_wait1(); else cp_wait0();
        __syncthreads();
        if (c + 2 < nchunks) { issue((c + 2) % NSTAGE, c + 2); cp_commit(); }

        uint32_t st = sbase + (c % NSTAGE) * STAGE_B;
        #pragma unroll
        for (int k16 = 0; k16 < 2; k16++) {
            int kbase = k16 * 16 + kk_off;
            uint32_t bh[4][2];
            #pragma unroll
            for (int in2 = 0; in2 < 2; in2++) {
                int nrow = wn * 32 + in2 * 16 + row_off;
                uint32_t off = sw64((uint32_t)(nrow * 64 + kbase * 2));
                uint32_t t[4];
                ldm4(t, st + OB + off);
                bh[in2 * 2 + 0][0] = t[0]; bh[in2 * 2 + 0][1] = t[2];
                bh[in2 * 2 + 1][0] = t[1]; bh[in2 * 2 + 1][1] = t[3];
            }
            uint32_t af[4][4];
            #pragma unroll
            for (int im = 0; im < 4; im++) {
                int mrow = wm * 64 + im * 16 + row_off;
                ldm4(af[im], st + OA + sw64((uint32_t)(mrow * 64 + kbase * 2)));
            }
            #pragma unroll
            for (int im = 0; im < 4; im++)
                #pragma unroll
                for (int in = 0; in < 4; in++)
                    mma16816h(acc[im][in], af[im], bh[in]);
        }
        __syncthreads();
    }

    int r_in = lane >> 2;
    int c_in = (lane & 3) * 2;

    if (EPI == 0) {
        #pragma unroll
        for (int im = 0; im < 4; im++) {
            size_t gr0 = (size_t)(rb + wm * 64 + im * 16 + r_in);
            #pragma unroll
            for (int in = 0; in < 4; in++) {
                int cl = wn * 32 + in * 8 + c_in;
                float b0 = bias[cl], b1 = bias[cl + 1];
                float v0 = acc[im][in][0] + b0, v1 = acc[im][in][1] + b1;
                float v2 = acc[im][in][2] + b0, v3 = acc[im][in][3] + b1;
                *(uint32_t*)&Sh[gr0 * lds + ncoloff + cl] = pack_h2(v0, v1);
                *(uint32_t*)&Sh[(gr0 + 8) * lds + ncoloff + cl] = pack_h2(v2, v3);
            }
        }
    } else {
        float sv[4][2] = {}, qv[4][2] = {};
        #pragma unroll
        for (int im = 0; im < 4; im++) {
            size_t gr0 = (size_t)(rb + wm * 64 + im * 16 + r_in);
            #pragma unroll
            for (int in = 0; in < 4; in++) {
                int cl = wn * 32 + in * 8 + c_in;
                float b0 = bias[cl], b1 = bias[cl + 1];
                float2 rv0 = *(const float2*)(R + gr0 * DIM + cl);
                float2 rv1 = *(const float2*)(R + (gr0 + 8) * DIM + cl);
                float v0 = acc[im][in][0] + b0 + rv0.x;
                float v1 = acc[im][in][1] + b1 + rv0.y;
                float v2 = acc[im][in][2] + b0 + rv1.x;
                float v3 = acc[im][in][3] + b1 + rv1.y;
                acc[im][in][0] = v0; acc[im][in][1] = v1;
                acc[im][in][2] = v2; acc[im][in][3] = v3;
                sv[im][0] += v0 + v1; qv[im][0] += v0 * v0 + v1 * v1;
                sv[im][1] += v2 + v3; qv[im][1] += v2 * v2 + v3 * v3;
            }
        }
        #pragma unroll
        for (int im = 0; im < 4; im++)
            #pragma unroll
            for (int h2 = 0; h2 < 2; h2++) {
                float s = sv[im][h2], q = qv[im][h2];
                s += __shfl_xor_sync(0xffffffffu, s, 1);
                s += __shfl_xor_sync(0xffffffffu, s, 2);
                q += __shfl_xor_sync(0xffffffffu, q, 1);
                q += __shfl_xor_sync(0xffffffffu, q, 2);
                if ((lane & 3) == 0) {
                    int rl = wm * 64 + im * 16 + r_in + h2 * 8;
                    s_sp[rl][wn] = s;
                    s_sq[rl][wn] = q;
                }
            }
        __syncthreads();
        float mn[4][2], rs[4][2];
        #pragma unroll
        for (int im = 0; im < 4; im++)
            #pragma unroll
            for (int h2 = 0; h2 < 2; h2++) {
                int rl = wm * 64 + im * 16 + r_in + h2 * 8;
                float s = s_sp[rl][0] + s_sp[rl][1] + s_sp[rl][2] + s_sp[rl][3];
                float q = s_sq[rl][0] + s_sq[rl][1] + s_sq[rl][2] + s_sq[rl][3];
                float m = s * (1.f / 128.f);
                float var = q * (1.f / 128.f) - m * m;
                mn[im][h2] = m;
                rs[im][h2] = rsqrtf(var + EPSV);
            }
        #pragma unroll
        for (int im = 0; im < 4; im++) {
            size_t gr0 = (size_t)(rb + wm * 64 + im * 16 + r_in);
            #pragma unroll
            for (int in = 0; in < 4; in++) {
                int cl = wn * 32 + in * 8 + c_in;
                float g0 = gam[cl], g1 = gam[cl + 1];
                float e0 = bet[cl], e1 = bet[cl + 1];
                float o0 = (acc[im][in][0] - mn[im][0]) * rs[im][0] * g0 + e0;
                float o1 = (acc[im][in][1] - mn[im][0]) * rs[im][0] * g1 + e1;
                float o2 = (acc[im][in][2] - mn[im][1]) * rs[im][1] * g0 + e0;
                float o3 = (acc[im][in][3] - mn[im][1]) * rs[im][1] * g1 + e1;
                *(float2*)(C + gr0 * ldc + cl) = make_float2(o0, o1);
                *(float2*)(C + (gr0 + 8) * ldc + cl) = make_float2(o2, o3);
                *(uint32_t*)&Sh[gr0 * lds + cl] = pack_h2(o0, o1);
                *(uint32_t*)&Sh[(gr0 + 8) * lds + cl] = pack_h2(o2, o3);
            }
        }
    }
}

// Generic GEMM kernel (Wo-LN)
template <int EPI>
__global__ __launch_bounds__(256, 2) void gemm_cp_kernel(
    int absel, int lda, int slotbase, int kchunks,
    const float* __restrict__ bias, int rsel,
    const float* __restrict__ gam, const float* __restrict__ bet,
    int csel, int ldc, int ssel, int lds)
{
    extern __shared__ char dsm[];
    int nb = blockIdx.x;
    int rb = blockIdx.y * 128;
    const __half* Ah = selh(absel);
    __half* Sh = selh(ssel);
    const __half* Ws =
        g_Wt + ((size_t)slotbase + (size_t)nb * kchunks) * SLOT_ELE;
    gemm_cp_core<EPI>(dsm, Ah, lda, Ws, kchunks,
                      bias + nb * 128,
                      rsel >= 0 ? self32(rsel) : nullptr, gam, bet,
                      csel >= 0 ? self32(csel) : nullptr, ldc,
                      Sh, lds, nb * 128, rb);
}

// QKV fused: blockIdx.x selects q/k/v (co-scheduled -> A L2 reuse)
__global__ __launch_bounds__(256, 2) void qkv_cp_kernel(
    int lslot, const float* __restrict__ bq,
    const float* __restrict__ bk, const float* __restrict__ bv)
{
    extern __shared__ char dsm[];
    int which = blockIdx.x;
    int rb = blockIdx.y * 128;
    const __half* Ws = g_Wt + (size_t)(lslot + which * 4) * SLOT_ELE;
    const float* bias = (which == 0) ? bq : (which == 1) ? bk : bv;
    __half* Sh = (which == 0) ? g_Qh : (which == 1) ? g_Kh : g_Vh;
    gemm_cp_core<0>(dsm, g_Xs, DIM, Ws, 4, bias,
                    nullptr, nullptr, nullptr, nullptr, 0,
                    Sh, DIM, 0, rb);
}

// ---------------------------------------------------------------------------
// Fused FFN: out = LN(relu(h@W1+b1)@W2 + b2 + h), hidden never leaves smem.
// M=64 per block, 4 warps, warp tile 64x32. 8 hid-chunks of 128.
// Chunk sequence c=0..63: j=c>>3, half=(c>>2)&1 (0:W1-G1, 1:W2-G2), kc=c&3.
// ---------------------------------------------------------------------------
#define FF_CHUNK(ACC) do {                                                   \
    _Pragma("unroll")                                                        \
    for (int k16 = 0; k16 < 2; k16++) {                                      \
        int kbase = k16 * 16 + kk_off;                                       \
        uint32_t bh[4][2];                                                   \
        _Pragma("unroll")                                                    \
        for (int in2 = 0; in2 < 2; in2++) {                                  \
            int nrow = wn * 32 + in2 * 16 + row_off;                         \
            uint32_t t[4];                                                   \
            ldm4(t, stB + sw64((uint32_t)(nrow * 64 + kbase * 2)));          \
            bh[in2 * 2 + 0][0] = t[0]; bh[in2 * 2 + 0][1] = t[2];            \
            bh[in2 * 2 + 1][0] = t[1]; bh[in2 * 2 + 1][1] = t[3];            \
        }                                                                    \
        uint32_t af[4][4];                                                   \
        _Pragma("unroll")                                                    \
        for (int im = 0; im < 4; im++) {                                     \
            int mrow = im * 16 + row_off;                                    \
            ldm4(af[im], stA + sw64((uint32_t)(mrow * 64 + kbase * 2)));     \
        }                                                                    \
        _Pragma("unroll")                                                    \
        for (int im = 0; im < 4; im++)                                       \
            _Pragma("unroll")                                                \
            for (int in = 0; in < 4; in++)                                   \
                mma16816h(ACC[im][in], af[im], bh[in]);                      \
    }                                                                        \
} while (0)

__global__ __launch_bounds__(128, 3) void ffn_fused_kernel(
    int lbase,
    const float* __restrict__ B1, const float* __restrict__ B2,
    const float* __restrict__ gam, const float* __restrict__ bet)
{
    extern __shared__ char dsm[];
    __shared__ float s_sp[64][4];
    __shared__ float s_sq[64][4];

    uint32_t raw_u = smem_u32(dsm);
    uint32_t sbase = (raw_u + 1023) & ~1023u;
    char* dsm_al = dsm + (sbase - raw_u);

    int tid = threadIdx.x;
    int wn = tid >> 5, lane = tid & 31;
    int rb = blockIdx.x * 64;

    int mt = lane >> 3, rr = lane & 7;
    int row_off = ((mt & 1) << 3) + rr;
    int kk_off = (mt >> 1) << 3;
    int r_in = lane >> 2;
    int c_in = (lane & 3) * 2;

    const char* wbase = (const char*)(g_Wt + (size_t)(lbase + 16) * SLOT_ELE);

    // load h tile: 64 rows x 128 halves into 4 k-chunks (group 1)
    const __half* hsrc = g_Hs + (size_t)rb * DIM;
    #pragma unroll
    for (int p = 0; p < 8; p++) {
        int g = p * 128 + tid;             // 0..1023
        int kc = g >> 8, r = (g >> 2) & 63, kq = (g & 3) * 8;
        cpa16(sbase + FF_H + kc * 4096 + sw64((uint32_t)(r * 64 + kq * 2)),
              hsrc + (size_t)r * DIM + kc * 32 + kq);
    }
    cp_commit();

    auto issueB = [&](int buf, int c) {
        int j = c >> 3, half = (c >> 2) & 1, kc = c & 3;
        const char* bs = wbase + (size_t)((half ? 32 : 0) + j * 4 + kc) * 8192;
        uint32_t st = sbase + FF_B + buf * FF_STAGE;
        #pragma unroll
        for (int p = 0; p < 4; p++) {
            uint32_t off = (uint32_t)((p * 128 + tid) * 16);
            cpa16(st + off, bs + off);
        }
    };

    issueB(0, 0); cp_commit();
    issueB(1, 1); cp_commit();

    float oacc[4][4][4];
    float g1[4][4][4];
    #pragma unroll
    for (int i = 0; i < 4; i++)
        #pragma unroll
        for (int j2 = 0; j2 < 4; j2++)
            #pragma unroll
            for (int r = 0; r < 4; r++) oacc[i][j2][r] = 0.f;

    for (int c = 0; c < 64; c++) {
        int j = c >> 3, half = (c >> 2) & 1, kc = c & 3;
        if (c + 1 < 64) cp_wait1(); else cp_wait0();
        __syncthreads();
        if (c + 2 < 64) { issueB((c + 2) % 3, c + 2); cp_commit(); }

        uint32_t stB = sbase + FF_B + (c % 3) * FF_STAGE;
        uint32_t stA = sbase + (half ? FF_HJ : FF_H) + kc * 4096;

        if (half == 0) {
            if (kc == 0) {
                #pragma unroll
                for (int i = 0; i < 4; i++)
                    #pragma unroll
                    for (int j2 = 0; j2 < 4; j2++)
                        #pragma unroll
                        for (int r = 0; r < 4; r++) g1[i][j2][r] = 0.f;
            }
            FF_CHUNK(g1);
            if (kc == 3) {
                // bias + relu -> Hj smem (fp16, A-layout: warp wn owns chunk wn)
                #pragma unroll
                for (int im = 0; im < 4; im++)
                    #pragma unroll
                    for (int in = 0; in < 4; in++) {
                        int cl = wn * 32 + in * 8 + c_in;
                        float bb0 = B1[j * 128 + cl];
                        float bb1 = B1[j * 128 + cl + 1];
                        float v0 = fmaxf(g1[im][in][0] + bb0, 0.f);
                        float v1 = fmaxf(g1[im][in][1] + bb1, 0.f);
                        float v2 = fmaxf(g1[im][in][2] + bb0, 0.f);
                        float v3 = fmaxf(g1[im][in][3] + bb1, 0.f);
                        int r0 = im * 16 + r_in;
                        int cc = in * 8 + c_in;
                        *(uint32_t*)(dsm_al + FF_HJ + wn * 4096 +
                            sw64((uint32_t)(r0 * 64 + cc * 2))) = pack_h2(v0, v1);
                        *(uint32_t*)(dsm_al + FF_HJ + wn * 4096 +
                            sw64((uint32_t)((r0 + 8) * 64 + cc * 2))) = pack_h2(v2, v3);
                    }
            }
        } else {
            FF_CHUNK(oacc);
        }
        __syncthreads();
    }

    // ---- LN epilogue: + b2 + residual h (g_Kb fp32), write g_X + g_Xs ----
    float sv[4][2] = {}, qv[4][2] = {};
    #pragma unroll
    for (int im = 0; im < 4; im++) {
        size_t gr0 = (size_t)(rb + im * 16 + r_in);
        #pragma unroll
        for (int in = 0; in < 4; in++) {
            int cl = wn * 32 + in * 8 + c_in;
            float b0 = B2[cl], b1v = B2[cl + 1];
            float2 rv0 = *(const float2*)(g_Kb + gr0 * DIM + cl);
            float2 rv1 = *(const float2*)(g_Kb + (gr0 + 8) * DIM + cl);
            float v0 = oacc[im][in][0] + b0 + rv0.x;
            float v1 = oacc[im][in][1] + b1v + rv0.y;
            float v2 = oacc[im][in][2] + b0 + rv1.x;
            float v3 = oacc[im][in][3] + b1v + rv1.y;
            oacc[im][in][0] = v0; oacc[im][in][1] = v1;
            oacc[im][in][2] = v2; oacc[im][in][3] = v3;
            sv[im][0] += v0 + v1; qv[im][0] += v0 * v0 + v1 * v1;
            sv[im][1] += v2 + v3; qv[im][1] += v2 * v2 + v3 * v3;
        }
    }
    #pragma unroll
    for (int im = 0; im < 4; im++)
        #pragma unroll
        for (int h2 = 0; h2 < 2; h2++) {
            float s = sv[im][h2], q = qv[im][h2];
            s += __shfl_xor_sync(0xffffffffu, s, 1);
            s += __shfl_xor_sync(0xffffffffu, s, 2);
            q += __shfl_xor_sync(0xffffffffu, q, 1);
            q += __shfl_xor_sync(0xffffffffu, q, 2);
            if ((lane & 3) == 0) {
                int rl = im * 16 + r_in + h2 * 8;
                s_sp[rl][wn] = s;
                s_sq[rl][wn] = q;
            }
        }
    __syncthreads();
    float mn[4][2], rs[4][2];
    #pragma unroll
    for (int im = 0; im < 4; im++)
        #pragma unroll
        for (int h2 = 0; h2 < 2; h2++) {
            int rl = im * 16 + r_in + h2 * 8;
            float s = s_sp[rl][0] + s_sp[rl][1] + s_sp[rl][2] + s_sp[rl][3];
            float q = s_sq[rl][0] + s_sq[rl][1] + s_sq[rl][2] + s_sq[rl][3];
            float m = s * (1.f / 128.f);
            float var = q * (1.f / 128.f) - m * m;
            mn[im][h2] = m;
            rs[im][h2] = rsqrtf(var + EPSV);
        }
    #pragma unroll
    for (int im = 0; im < 4; im++) {
        size_t gr0 = (size_t)(rb + im * 16 + r_in);
        #pragma unroll
        for (int in = 0; in < 4; in++) {
            int cl = wn * 32 + in * 8 + c_in;
            float g0 = gam[cl], g1v = gam[cl + 1];
            float e0 = bet[cl], e1 = bet[cl + 1];
            float o0 = (oacc[im][in][0] - mn[im][0]) * rs[im][0] * g0 + e0;
            float o1 = (oacc[im][in][1] - mn[im][0]) * rs[im][0] * g1v + e1;
            float o2 = (oacc[im][in][2] - mn[im][1]) * rs[im][1] * g0 + e0;
            float o3 = (oacc[im][in][3] - mn[im][1]) * rs[im][1] * g1v + e1;
            *(float2*)(g_X + gr0 * DIM + cl) = make_float2(o0, o1);
            *(float2*)(g_X + (gr0 + 8) * DIM + cl) = make_float2(o2, o3);
            *(uint32_t*)&g_Xs[gr0 * DIM + cl] = pack_h2(o0, o1);
            *(uint32_t*)&g_Xs[(gr0 + 8) * DIM + cl] = pack_h2(o2, o3);
        }
    }
}

// ---------------------------------------------------------------------------
// Attention: one warp per 16x16 unit; fp16 in (g_Qh/g_Kh/g_Vh), fp16 out (g_Cs)
// ---------------------------------------------------------------------------
__global__ __launch_bounds__(256) void attn_kernel() {
    __shared__ float s_q[8][256];
    __shared__ float s_k[8][256];
    __shared__ float s_v[8][256];

    int w = threadIdx.x >> 5, lane = threadIdx.x & 31;
    size_t n = (size_t)blockIdx.x * 8 + w;
    size_t bse = n * 256;

    {
        uint4 qv = *(const uint4*)(g_Qh + bse + lane * 8);
        uint4 kv = *(const uint4*)(g_Kh + bse + lane * 8);
        uint4 vv = *(const uint4*)(g_Vh + bse + lane * 8);
        const uint32_t* qp = (const uint32_t*)&qv;
        const uint32_t* kp = (const uint32_t*)&kv;
        const uint32_t* vp = (const uint32_t*)&vv;
        #pragma unroll
        for (int u = 0; u < 4; u++) {
            float2 f;
            f = __half22float2(*(const __half2*)&qp[u]);
            s_q[w][lane * 8 + u * 2] = f.x; s_q[w][lane * 8 + u * 2 + 1] = f.y;
            f = __half22float2(*(const __half2*)&kp[u]);
            s_k[w][lane * 8 + u * 2] = f.x; s_k[w][lane * 8 + u * 2 + 1] = f.y;
            f = __half22float2(*(const __half2*)&vp[u]);
            s_v[w][lane * 8 + u * 2] = f.x; s_v[w][lane * 8 + u * 2 + 1] = f.y;
        }
    }
    __syncwarp();

    int i = lane >> 1;
    int jb = (lane & 1) * 8;

    float qr[16];
    #pragma unroll
    for (int u = 0; u < 4; u++) {
        float4 t4 = *(const float4*)&s_q[w][i * 16 + u * 4];
        qr[u * 4 + 0] = t4.x; qr[u * 4 + 1] = t4.y;
        qr[u * 4 + 2] = t4.z; qr[u * 4 + 3] = t4.w;
    }

    float sc[8];
    #pragma unroll
    for (int j = 0; j < 8; j++) {
        const float* kr = &s_k[w][(jb + j) * 16];
        float dd = 0.f;
        #pragma unroll
        for (int u = 0; u < 16; u++) dd = fmaf(qr[u], kr[u], dd);
        sc[j] = dd * 0.25f;
    }

    float mx = sc[0];
    #pragma unroll
    for (int j = 1; j < 8; j++) mx = fmaxf(mx, sc[j]);
    mx = fmaxf(mx, __shfl_xor_sync(0xffffffffu, mx, 1));

    float sum = 0.f;
    #pragma unroll
    for (int j = 0; j < 8; j++) { sc[j] = __expf(sc[j] - mx); sum += sc[j]; }
    sum += __shfl_xor_sync(0xffffffffu, sum, 1);
    float inv = 1.f / sum;

    float acc[16] = {};
    #pragma unroll
    for (int j = 0; j < 8; j++) {
        float p = sc[j] * inv;
        const float* vr = &s_v[w][(jb + j) * 16];
        #pragma unroll
        for (int u = 0; u < 16; u++) acc[u] = fmaf(p, vr[u], acc[u]);
    }
    #pragma unroll
    for (int u = 0; u < 16; u++)
        acc[u] += __shfl_xor_sync(0xffffffffu, acc[u], 1);

    int db = (lane & 1) * 8;
    size_t e = bse + i * 16 + db;
    *(uint4*)(&g_Cs[e]) = make_uint4(
        pack_h2(acc[db + 0], acc[db + 1]), pack_h2(acc[db + 2], acc[db + 3]),
        pack_h2(acc[db + 4], acc[db + 5]), pack_h2(acc[db + 6], acc[db + 7]));
}

// ---------------------------------------------------------------------------
// Head
// ---------------------------------------------------------------------------
__global__ __launch_bounds__(128) void numproj_kernel(
    const float* __restrict__ num, const float* __restrict__ Wn,
    const float* __restrict__ bnum)
{
    __shared__ float sn[NUMF];
    int b = blockIdx.x, t = threadIdx.x;
    if (t < NUMF) sn[t] = num[(size_t)b * NUMF + t];
    __syncthreads();
    float acc = bnum[t];
    #pragma unroll 1
    for (int k = 0; k < NUMF; k++)
        acc = fmaf(sn[k], Wn[k * DIM + t], acc);
    g_Np[(size_t)b * DIM + t] = acc;
}

__global__ __launch_bounds__(256) void bn_partial_kernel() {
    int j = blockIdx.x, t = threadIdx.x;
    int col = t & 127, half = t >> 7;
    float s = 0.f, q = 0.f;
    for (int i = 0; i < 64; i++) {
        float v = g_Np[(size_t)(j * 128 + half * 64 + i) * DIM + col];
        s += v; q += v * v;
    }
    __shared__ float ss[256], sq[256];
    ss[t] = s; sq[t] = q;
    __syncthreads();
    if (half == 0) {
        g_bnp[j * DIM + col]            = ss[t] + ss[t + 128];
        g_bnp[64 * DIM + j * DIM + col] = sq[t] + sq[t + 128];
    }
}

__global__ __launch_bounds__(128) void bn_final_kernel(
    const float* __restrict__ gamma, const float* __restrict__ beta)
{
    int c = threadIdx.x;
    float s = 0.f, q = 0.f;
    for (int j = 0; j < 64; j++) {
        s += g_bnp[j * DIM + c];
        q += g_bnp[64 * DIM + j * DIM + c];
    }
    float mu = s * (1.f / 8192.f);
    float var = q * (1.f / 8192.f) - mu * mu;
    float a = gamma[c] * rsqrtf(var + EPSV);
    g_bns[c] = a;
    g_bns[DIM + c] = beta[c] - mu * a;
}

__global__ __launch_bounds__(256) void final_kernel(
    const float* __restrict__ gcn, const float* __restrict__ Wf,
    const float* __restrict__ bf, float* __restrict__ out)
{
    int b = blockIdx.x, t = threadIdx.x;
    const float* xr = g_X + (size_t)b * (SEQ * DIM);
    float acc = 0.f;
    #pragma unroll
    for (int i = 0; i < 8; i++) {
        int idx = t + 256 * i;
        acc = fmaf(xr[idx], Wf[idx], acc);
    }
    if (t < GCN)
        acc = fmaf(gcn[(size_t)b * GCN + t], Wf[SEQ * DIM + t], acc);
    if (t < DIM) {
        float v = g_Np[(size_t)b * DIM + t] * g_bns[t] + g_bns[DIM + t];
        acc = fmaf(v, Wf[SEQ * DIM + GCN + t], acc);
    }
    acc = warp_red(acc);
    __shared__ float red[8];
    if ((t & 31) == 0) red[t >> 5] = acc;
    __syncthreads();
    if (t == 0) {
        float z = red[0] + red[1] + red[2] + red[3]
                + red[4] + red[5] + red[6] + red[7] + bf[0];
        out[b] = 1.f / (1.f + expf(-z));
    }
}

// ---------------------------------------------------------------------------
// Launch
// ---------------------------------------------------------------------------
extern "C" void kernel_launch(void* const* d_in, const int* in_sizes, int n_in,
                              void* d_out, int out_size)
{
    const float* x    = (const float*)d_in[0];
    const float* gcn  = (const float*)d_in[1];
    const float* num  = (const float*)d_in[2];
    const float* Wq   = (const float*)d_in[3];
    const float* bq   = (const float*)d_in[4];
    const float* Wk   = (const float*)d_in[5];
    const float* bk   = (const float*)d_in[6];
    const float* Wv   = (const float*)d_in[7];
    const float* bv   = (const float*)d_in[8];
    const float* Wo   = (const float*)d_in[9];
    const float* bo   = (const float*)d_in[10];
    const float* ln1g = (const float*)d_in[11];
    const float* ln1b = (const float*)d_in[12];
    const float* W1   = (const float*)d_in[13];
    const float* b1   = (const float*)d_in[14];
    const float* W2   = (const float*)d_in[15];
    const float* b2   = (const float*)d_in[16];
    const float* ln2g = (const float*)d_in[17];
    const float* ln2b = (const float*)d_in[18];
    const float* Wn   = (const float*)d_in[19];
    const float* bnum = (const float*)d_in[20];
    const float* bng  = (const float*)d_in[21];
    const float* bnb  = (const float*)d_in[22];
    const float* Wf   = (const float*)d_in[23];
    const float* bf   = (const float*)d_in[24];
    float* out = (float*)d_out;

    cudaFuncSetAttribute(qkv_cp_kernel,
        cudaFuncAttributeMaxDynamicSharedMemorySize, DSMEM_BYTES);
    cudaFuncSetAttribute(gemm_cp_kernel<2>,
        cudaFuncAttributeMaxDynamicSharedMemorySize, DSMEM_BYTES);
    cudaFuncSetAttribute(ffn_fused_kernel,
        cudaFuncAttributeMaxDynamicSharedMemorySize, DSMEM_FF);

    pe_init_kernel<<<2, 1024>>>();
    prep_weights_kernel<<<SLOTS_TOTAL, 256>>>(Wq, Wk, Wv, Wo, W1, W2);
    add_pe_kernel<<<16384, 256>>>(x);

    const int RB = MTOT / 128;   // 1024 row blocks
    for (int l = 0; l < 2; l++) {
        int lb = l * 80;
        // QKV: g_Xs -> Qh,Kh,Vh (fp16)
        qkv_cp_kernel<<<dim3(3, RB), 256, DSMEM_BYTES>>>(
            lb, bq + l * DIM, bk + l * DIM, bv + l * DIM);
        // attention: fp16 q,k,v -> ctx fp16 (g_Cs)
        attn_kernel<<<MTOT / 16, 256>>>();
        // h = LN(ctx @ Wo + bo + X): fp32 -> g_Kb, fp16 -> g_Hs
        gemm_cp_kernel<2><<<dim3(1, RB), 256, DSMEM_BYTES>>>(
            1, DIM, lb + 12, 4, bo + l * DIM, 0,
            ln1g + l * DIM, ln1b + l * DIM, 2, DIM, 2, DIM);
        // fused FFN: out = LN(relu(h@W1+b1)@W2 + b2 + h) -> g_X + g_Xs
        ffn_fused_kernel<<<MTOT / 64, 128, DSMEM_FF>>>(
            lb, b1 + l * HID, b2 + l * DIM,
            ln2g + l * DIM, ln2b + l * DIM);
    }

    numproj_kernel<<<BATCH, 128>>>(num, Wn, bnum);
    bn_partial_kernel<<<64, 256>>>();
    bn_final_kernel<<<1, 128>>>(bng, bnb);
    final_kernel<<<BATCH, 256>>>(gcn, Wf, bf, out);
}

// round 16
// speedup vs baseline: 1.4014x; 1.1501x over previous
#include <cuda_runtime.h>
#include <cuda_fp16.h>
#include <math.h>
#include <stdint.h>

// ---------------------------------------------------------------------------
// Problem constants
// ---------------------------------------------------------------------------
#define BATCH 8192
#define SEQ   16
#define DIM   128
#define MTOT  (BATCH * SEQ)        // 131072 rows
#define HID   1024
#define GCN   40
#define NUMF  103
#define EPSV  1e-5f

// Weight-tile store: each "slot" = one 128(N)x32(K) fp16 tile,
// SW64-swizzled 64B rows — ldmatrix-ready. 4096 fp16 = 8KB.
#define SLOT_ELE    4096
#define SLOTS_TOTAL 160              // 80 per layer x 2 layers
// per-layer map: Wq:0-3 Wk:4-7 Wv:8-11 Wo:12-15 W1:16+nb*4+kc W2:48+kc

// Generic GEMM (Wo): tile 128x128, Kchunk=64 (2 sub-tiles of 32), 8 warps.
#define OA    0u
#define OB    16384u
#define STAGE_B 32768u
#define NSTAGE 3
#define DSMEM_BYTES (1024 + NSTAGE * STAGE_B)   // 99328

// QKV fused: A resident 32KB + B ring 3x16KB
#define QKV_A   0u
#define QKV_B   32768u
#define QKV_STG 16384u
#define DSMEM_QKV (1024 + 32768 + 3 * QKV_STG)  // 82944

// Fused-FFN smem (R14-proven): h 16KB + Hj 16KB + B-ring 3x8KB
#define FF_STAGE 8192u
#define FF_H  0u
#define FF_HJ 16384u
#define FF_B  32768u
#define DSMEM_FF (1024 + 32768 + 3 * FF_STAGE)   // 58368

// ---------------------------------------------------------------------------
// Scratch
// ---------------------------------------------------------------------------
__device__ float g_X[MTOT * DIM];
__device__ float g_Kb[MTOT * DIM];
__device__ float g_Np[BATCH * DIM];
__device__ float g_bnp[2 * 64 * DIM];
__device__ float g_bns[2 * DIM];
__device__ float g_PE[SEQ * DIM];
__device__ __half g_Wt[(size_t)SLOTS_TOTAL * SLOT_ELE];
__device__ __half g_Xs[(size_t)MTOT * DIM];   // QKV input
__device__ __half g_Cs[(size_t)MTOT * DIM];   // ctx -> Wo input
__device__ __half g_Hs[(size_t)MTOT * DIM];   // h -> FFN input
__device__ __half g_Qh[(size_t)MTOT * DIM];   // q
__device__ __half g_Kh[(size_t)MTOT * DIM];   // k
__device__ __half g_Vh[(size_t)MTOT * DIM];   // v

__device__ __forceinline__ float warp_red(float v) {
    #pragma unroll
    for (int o = 16; o; o >>= 1) v += __shfl_xor_sync(0xffffffffu, v, o);
    return v;
}

// ---------------------------------------------------------------------------
// PTX helpers
// ---------------------------------------------------------------------------
__device__ __forceinline__ uint32_t smem_u32(const void* p) {
    uint32_t a;
    asm("{ .reg .u64 t; cvta.to.shared.u64 t, %1; cvt.u32.u64 %0, t; }"
        : "=r"(a) : "l"(p));
    return a;
}

__device__ __forceinline__ void ldm4(uint32_t* r, uint32_t addr) {
    asm volatile("ldmatrix.sync.aligned.m8n8.x4.shared.b16 {%0,%1,%2,%3}, [%4];"
                 : "=r"(r[0]), "=r"(r[1]), "=r"(r[2]), "=r"(r[3]) : "r"(addr));
}
__device__ __forceinline__ void ldm2(uint32_t* r, uint32_t addr) {
    asm volatile("ldmatrix.sync.aligned.m8n8.x2.shared.b16 {%0,%1}, [%2];"
                 : "=r"(r[0]), "=r"(r[1]) : "r"(addr));
}
__device__ __forceinline__ void ldm2t(uint32_t* r, uint32_t addr) {
    asm volatile("ldmatrix.sync.aligned.m8n8.x2.trans.shared.b16 {%0,%1}, [%2];"
                 : "=r"(r[0]), "=r"(r[1]) : "r"(addr));
}

__device__ __forceinline__ void mma16816h(float* c, const uint32_t* a,
                                          const uint32_t* b) {
    asm volatile(
        "mma.sync.aligned.m16n8k16.row.col.f32.f16.f16.f32 "
        "{%0,%1,%2,%3}, {%4,%5,%6,%7}, {%8,%9}, {%0,%1,%2,%3};"
        : "+f"(c[0]), "+f"(c[1]), "+f"(c[2]), "+f"(c[3])
        : "r"(a[0]), "r"(a[1]), "r"(a[2]), "r"(a[3]), "r"(b[0]), "r"(b[1]));
}

__device__ __forceinline__ void cpa16(uint32_t dst, const void* src) {
    asm volatile("{ .reg .u64 g; cvta.to.global.u64 g, %1; "
                 "cp.async.cg.shared.global [%0], [g], 16; }"
                 :: "r"(dst), "l"(src));
}
__device__ __forceinline__ void cp_commit() {
    asm volatile("cp.async.commit_group;" ::: "memory");
}
__device__ __forceinline__ void cp_wait0() {
    asm volatile("cp.async.wait_group 0;" ::: "memory");
}
__device__ __forceinline__ void cp_wait1() {
    asm volatile("cp.async.wait_group 1;" ::: "memory");
}

__device__ __forceinline__ uint32_t sw64(uint32_t off) {
    return off ^ ((off >> 3) & 0x30);
}

__device__ __forceinline__ uint32_t pack_h2(float a, float b) {
    uint32_t h;
    asm("cvt.rn.f16x2.f32 %0, %1, %2;" : "=r"(h) : "f"(b), "f"(a));
    return h;
}

// ---------------------------------------------------------------------------
// PE init + add
// ---------------------------------------------------------------------------
__global__ void pe_init_kernel() {
    int idx = blockIdx.x * 1024 + threadIdx.x;
    if (idx < SEQ * DIM) {
        int s = idx >> 7, d = idx & 127;
        double e = (double)((d >> 1) * 2) / (double)DIM;
        double p = (double)s / pow(10000.0, e);
        g_PE[idx] = (float)((d & 1) ? cos(p) : sin(p));
    }
}

__global__ void add_pe_kernel(const float* __restrict__ x) {
    size_t i4 = (size_t)blockIdx.x * 256 + threadIdx.x;
    float4 xv = ((const float4*)x)[i4];
    int sd = (int)((i4 * 4) & 2047);
    float4 pv = *(const float4*)(g_PE + sd);
    xv.x += pv.x; xv.y += pv.y; xv.z += pv.z; xv.w += pv.w;
    ((float4*)g_X)[i4] = xv;
    *(uint2*)(&g_Xs[i4 * 4]) =
        make_uint2(pack_h2(xv.x, xv.y), pack_h2(xv.z, xv.w));
}

// ---------------------------------------------------------------------------
// Weight prep (unchanged slot format)
// ---------------------------------------------------------------------------
__global__ __launch_bounds__(256) void prep_weights_kernel(
    const float* __restrict__ Wq, const float* __restrict__ Wk,
    const float* __restrict__ Wv, const float* __restrict__ Wo,
    const float* __restrict__ W1, const float* __restrict__ W2)
{
    int slot = blockIdx.x;
    int l = slot / 80, s = slot % 80;
    const float* W; int Nmat, nb, kc;
    if (s < 16) {
        int m = s >> 2; kc = s & 3; nb = 0; Nmat = 128;
        const float* mats[4] = {Wq, Wk, Wv, Wo};
        W = mats[m] + (size_t)l * DIM * DIM;
    } else if (s < 48) {
        int t = s - 16; nb = t >> 2; kc = t & 3; Nmat = HID;
        W = W1 + (size_t)l * DIM * HID;
    } else {
        int t = s - 48; nb = 0; kc = t; Nmat = 128;
        W = W2 + (size_t)l * HID * DIM;
    }
    char* tile = (char*)(g_Wt + (size_t)slot * SLOT_ELE);

    int g = threadIdx.x;
    #pragma unroll
    for (int it = 0; it < 2; it++, g += 256) {
        int n_local = g >> 2;
        int kq = (g & 3) * 8;
        uint4 hi4;
        uint32_t* hp = (uint32_t*)&hi4;
        #pragma unroll
        for (int u = 0; u < 4; u++) {
            float v0 = W[(size_t)(kc * 32 + kq + u * 2 + 0) * Nmat + nb * 128 + n_local];
            float v1 = W[(size_t)(kc * 32 + kq + u * 2 + 1) * Nmat + nb * 128 + n_local];
            hp[u] = pack_h2(v0, v1);
        }
        *(uint4*)(tile + sw64((uint32_t)(n_local * 64 + kq * 2))) = hi4;
    }
}

// ---------------------------------------------------------------------------
// Shared compute helper: one K16 step of the 64x32-warp-tile MMA
// ---------------------------------------------------------------------------
#define K16_STEP(stA_, stB_, kb_, ACC) do {                                  \
    uint32_t bh[4][2];                                                       \
    _Pragma("unroll")                                                        \
    for (int in2 = 0; in2 < 2; in2++) {                                      \
        int nrow = wn * 32 + in2 * 16 + row_off;                             \
        uint32_t t[4];                                                       \
        ldm4(t, (stB_) + sw64((uint32_t)(nrow * 64 + (kb_) * 2)));           \
        bh[in2 * 2 + 0][0] = t[0]; bh[in2 * 2 + 0][1] = t[2];                \
        bh[in2 * 2 + 1][0] = t[1]; bh[in2 * 2 + 1][1] = t[3];                \
    }                                                                        \
    uint32_t af[4][4];                                                       \
    _Pragma("unroll")                                                        \
    for (int im = 0; im < 4; im++) {                                         \
        int mrow = wm * 64 + im * 16 + row_off;                              \
        ldm4(af[im], (stA_) + sw64((uint32_t)(mrow * 64 + (kb_) * 2)));      \
    }                                                                        \
    _Pragma("unroll")                                                        \
    for (int im = 0; im < 4; im++)                                           \
        _Pragma("unroll")                                                    \
        for (int in = 0; in < 4; in++)                                       \
            mma16816h(ACC[im][in], af[im], bh[in]);                          \
} while (0)

// ---------------------------------------------------------------------------
// Wo GEMM + LN (Kchunk=64): h = LN(ctx@Wo + bo + X) -> g_Kb (f32) + g_Hs (f16)
// ---------------------------------------------------------------------------
__global__ __launch_bounds__(256, 2) void wo_ln_kernel(
    int slotbase,
    const float* __restrict__ bias,
    const float* __restrict__ gam, const float* __restrict__ bet)
{
    extern __shared__ char dsm[];
    __shared__ float s_sp[128][4];
    __shared__ float s_sq[128][4];

    uint32_t raw_u = smem_u32(dsm);
    uint32_t sbase = (raw_u + 1023) & ~1023u;

    int tid = threadIdx.x;
    int wid = tid >> 5, lane = tid & 31;
    int wm = wid & 1, wn = wid >> 1;
    int rb = blockIdx.x * 128;

    int mt = lane >> 3, rr = lane & 7;
    int row_off = ((mt & 1) << 3) + rr;
    int kk_off = (mt >> 1) << 3;

    const __half* A = g_Cs;
    const char* bbase = (const char*)(g_Wt + (size_t)slotbase * SLOT_ELE);

    // hoisted A loader geometry: 4 granules/thread per chunk
    uint32_t ag_dst[4];
    const __half* ag_src[4];
    #pragma unroll
    for (int p = 0; p < 4; p++) {
        int g = p * 256 + tid;            // 0..1023
        int sub = g >> 9, idx = g & 511;
        int arow = idx >> 2, kq = (idx & 3) * 8;
        ag_dst[p] = sub * 8192 + sw64((uint32_t)(arow * 64 + kq * 2));
        ag_src[p] = A + (size_t)(rb + arow) * DIM + sub * 32 + kq;
    }

    float acc[4][4][4];
    #pragma unroll
    for (int i = 0; i < 4; i++)
        #pragma unroll
        for (int j = 0; j < 4; j++)
            #pragma unroll
            for (int r = 0; r < 4; r++) acc[i][j][r] = 0.f;

    auto issue = [&](int buf, int c) {
        uint32_t st = sbase + buf * STAGE_B;
        #pragma unroll
        for (int p = 0; p < 4; p++)
            cpa16(st + OA + ag_dst[p], ag_src[p] + c * 64);
        const char* bs = bbase + (size_t)c * 16384;
        #pragma unroll
        for (int p = 0; p < 4; p++) {
            uint32_t off = (uint32_t)((p * 256 + tid) * 16);
            cpa16(st + OB + off, bs + off);
        }
    };

    issue(0, 0); cp_commit();
    issue(1, 1); cp_commit();

    for (int c = 0; c < 2; c++) {
        if (c == 0) cp_wait1(); else cp_wait0();
        __syncthreads();
        uint32_t st = sbase + c * STAGE_B;
        #pragma unroll
        for (int k16 = 0; k16 < 4; k16++) {
            uint32_t so = (uint32_t)(k16 >> 1) * 8192;
            int kb = (k16 & 1) * 16 + kk_off;
            K16_STEP(st + OA + so, st + OB + so, kb, acc);
        }
        __syncthreads();
    }

    // LN epilogue (residual g_X)
    int r_in = lane >> 2, c_in = (lane & 3) * 2;
    float sv[4][2] = {}, qv[4][2] = {};
    #pragma unroll
    for (int im = 0; im < 4; im++) {
        size_t gr0 = (size_t)(rb + wm * 64 + im * 16 + r_in);
        #pragma unroll
        for (int in = 0; in < 4; in++) {
            int cl = wn * 32 + in * 8 + c_in;
            float b0 = bias[cl], b1 = bias[cl + 1];
            float2 rv0 = *(const float2*)(g_X + gr0 * DIM + cl);
            float2 rv1 = *(const float2*)(g_X + (gr0 + 8) * DIM + cl);
            float v0 = acc[im][in][0] + b0 + rv0.x;
            float v1 = acc[im][in][1] + b1 + rv0.y;
            float v2 = acc[im][in][2] + b0 + rv1.x;
            float v3 = acc[im][in][3] + b1 + rv1.y;
            acc[im][in][0] = v0; acc[im][in][1] = v1;
            acc[im][in][2] = v2; acc[im][in][3] = v3;
            sv[im][0] += v0 + v1; qv[im][0] += v0 * v0 + v1 * v1;
            sv[im][1] += v2 + v3; qv[im][1] += v2 * v2 + v3 * v3;
        }
    }
    #pragma unroll
    for (int im = 0; im < 4; im++)
        #pragma unroll
        for (int h2 = 0; h2 < 2; h2++) {
            float s = sv[im][h2], q = qv[im][h2];
            s += __shfl_xor_sync(0xffffffffu, s, 1);
            s += __shfl_xor_sync(0xffffffffu, s, 2);
            q += __shfl_xor_sync(0xffffffffu, q, 1);
            q += __shfl_xor_sync(0xffffffffu, q, 2);
            if ((lane & 3) == 0) {
                int rl = wm * 64 + im * 16 + r_in + h2 * 8;
                s_sp[rl][wn] = s;
                s_sq[rl][wn] = q;
            }
        }
    __syncthreads();
    float mn[4][2], rs[4][2];
    #pragma unroll
    for (int im = 0; im < 4; im++)
        #pragma unroll
        for (int h2 = 0; h2 < 2; h2++) {
            int rl = wm * 64 + im * 16 + r_in + h2 * 8;
            float s = s_sp[rl][0] + s_sp[rl][1] + s_sp[rl][2] + s_sp[rl][3];
            float q = s_sq[rl][0] + s_sq[rl][1] + s_sq[rl][2] + s_sq[rl][3];
            float m = s * (1.f / 128.f);
            float var = q * (1.f / 128.f) - m * m;
            mn[im][h2] = m;
            rs[im][h2] = rsqrtf(var + EPSV);
        }
    #pragma unroll
    for (int im = 0; im < 4; im++) {
        size_t gr0 = (size_t)(rb + wm * 64 + im * 16 + r_in);
        #pragma unroll
        for (int in = 0; in < 4; in++) {
            int cl = wn * 32 + in * 8 + c_in;
            float g0 = gam[cl], g1 = gam[cl + 1];
            float e0 = bet[cl], e1 = bet[cl + 1];
            float o0 = (acc[im][in][0] - mn[im][0]) * rs[im][0] * g0 + e0;
            float o1 = (acc[im][in][1] - mn[im][0]) * rs[im][0] * g1 + e1;
            float o2 = (acc[im][in][2] - mn[im][1]) * rs[im][1] * g0 + e0;
            float o3 = (acc[im][in][3] - mn[im][1]) * rs[im][1] * g1 + e1;
            *(float2*)(g_Kb + gr0 * DIM + cl) = make_float2(o0, o1);
            *(float2*)(g_Kb + (gr0 + 8) * DIM + cl) = make_float2(o2, o3);
            *(uint32_t*)&g_Hs[gr0 * DIM + cl] = pack_h2(o0, o1);
            *(uint32_t*)&g_Hs[(gr0 + 8) * DIM + cl] = pack_h2(o2, o3);
        }
    }
}

// ---------------------------------------------------------------------------
// Single-pass QKV: A (g_Xs) resident in smem, loop q/k/v weights.
// ---------------------------------------------------------------------------
__global__ __launch_bounds__(256, 2) void qkv_fused_kernel(
    int lbase, const float* __restrict__ bq,
    const float* __restrict__ bk, const float* __restrict__ bv)
{
    extern __shared__ char dsm[];
    uint32_t raw_u = smem_u32(dsm);
    uint32_t sbase = (raw_u + 1023) & ~1023u;

    int tid = threadIdx.x;
    int wid = tid >> 5, lane = tid & 31;
    int wm = wid & 1, wn = wid >> 1;
    int rb = blockIdx.x * 128;

    int mt = lane >> 3, rr = lane & 7;
    int row_off = ((mt & 1) << 3) + rr;
    int kk_off = (mt >> 1) << 3;
    int r_in = lane >> 2, c_in = (lane & 3) * 2;

    const char* wbase = (const char*)(g_Wt + (size_t)lbase * SLOT_ELE);

    // load full A tile (K=128, 4 sub-tiles of 8KB) + first two B chunks
    {
        const __half* asrc = g_Xs + (size_t)rb * DIM;
        #pragma unroll
        for (int p = 0; p < 8; p++) {
            int g = p * 256 + tid;        // 0..2047
            int st = g >> 9, idx = g & 511;
            int arow = idx >> 2, kq = (idx & 3) * 8;
            cpa16(sbase + QKV_A + st * 8192 + sw64((uint32_t)(arow * 64 + kq * 2)),
                  asrc + (size_t)arow * DIM + st * 32 + kq);
        }
    }
    auto issueB = [&](int buf, int c) {
        const char* bs = wbase + (size_t)c * 16384;   // chunk = 2 slots
        uint32_t st = sbase + QKV_B + buf * QKV_STG;
        #pragma unroll
        for (int p = 0; p < 4; p++) {
            uint32_t off = (uint32_t)((p * 256 + tid) * 16);
            cpa16(st + off, bs + off);
        }
    };
    issueB(0, 0); cp_commit();          // group: A + B0
    issueB(1, 1); cp_commit();

    float acc[4][4][4];
    #pragma unroll
    for (int i = 0; i < 4; i++)
        #pragma unroll
        for (int j = 0; j < 4; j++)
            #pragma unroll
            for (int r = 0; r < 4; r++) acc[i][j][r] = 0.f;

    for (int c = 0; c < 6; c++) {
        int w = c >> 1, part = c & 1;
        if (c + 1 < 6) cp_wait1(); else cp_wait0();
        __syncthreads();
        if (c + 2 < 6) { issueB((c + 2) % 3, c + 2); cp_commit(); }

        uint32_t stB = sbase + QKV_B + (c % 3) * QKV_STG;
        uint32_t stA = sbase + QKV_A + part * 16384;
        #pragma unroll
        for (int k16 = 0; k16 < 4; k16++) {
            uint32_t so = (uint32_t)(k16 >> 1) * 8192;
            int kb = (k16 & 1) * 16 + kk_off;
            K16_STEP(stA + so, stB + so, kb, acc);
        }

        if (part == 1) {
            __half* Sh = (w == 0) ? g_Qh : (w == 1) ? g_Kh : g_Vh;
            const float* bias = (w == 0) ? bq : (w == 1) ? bk : bv;
            #pragma unroll
            for (int im = 0; im < 4; im++) {
                size_t gr0 = (size_t)(rb + wm * 64 + im * 16 + r_in);
                #pragma unroll
                for (int in = 0; in < 4; in++) {
                    int cl = wn * 32 + in * 8 + c_in;
                    float b0 = bias[cl], b1 = bias[cl + 1];
                    *(uint32_t*)&Sh[gr0 * DIM + cl] =
                        pack_h2(acc[im][in][0] + b0, acc[im][in][1] + b1);
                    *(uint32_t*)&Sh[(gr0 + 8) * DIM + cl] =
                        pack_h2(acc[im][in][2] + b0, acc[im][in][3] + b1);
                    #pragma unroll
                    for (int r = 0; r < 4; r++) acc[im][in][r] = 0.f;
                }
            }
        }
        __syncthreads();
    }
}

// ---------------------------------------------------------------------------
// Tensor-core attention: one warp per 16x16 unit.
// S = q@k^T (2 mma), softmax (quad shfl), O = P@V (2 mma, V via ldmatrix.trans)
// ---------------------------------------------------------------------------
__global__ __launch_bounds__(256) void attn_tc_kernel() {
    __shared__ __align__(16) char sm[8 * 2304];   // per warp: q 768, k 768, v 768

    int w = threadIdx.x >> 5, lane = threadIdx.x & 31;
    size_t n = (size_t)blockIdx.x * 8 + w;
    size_t bse = n * 256;
    char* tb = sm + w * 2304;
    uint32_t qb = smem_u32(tb);

    // gmem -> smem (16 rows, 48B stride: conflict-free ldmatrix phases)
    {
        int row = lane >> 1, half = lane & 1;
        uint32_t doff = (uint32_t)(row * 48 + half * 16);
        size_t soff = bse + row * 16 + half * 8;
        *(uint4*)(tb + doff)        = *(const uint4*)(g_Qh + soff);
        *(uint4*)(tb + 768 + doff)  = *(const uint4*)(g_Kh + soff);
        *(uint4*)(tb + 1536 + doff) = *(const uint4*)(g_Vh + soff);
    }
    __syncwarp();

    // q: a-frag m16k16
    uint32_t aq[4];
    ldm4(aq, qb + (lane & 15) * 48 + (lane >> 4) * 16);
    // k: b-frags (col-major n8k16 = k's row-major; no trans)
    uint32_t bk0[2], bk1[2];
    {
        uint32_t addr = qb + 768 + (lane & 7) * 48 + ((lane >> 3) & 1) * 16;
        ldm2(bk0, addr);            // n = k-rows 0-7
        ldm2(bk1, addr + 8 * 48);   // n = k-rows 8-15
    }
    // V: b-frags via trans (n=d, k=j)
    uint32_t bv0[2], bv1[2];
    {
        uint32_t addr = qb + 1536 + (lane & 15) * 48;
        ldm2t(bv0, addr);           // d 0-7
        ldm2t(bv1, addr + 16);      // d 8-15
    }

    float s0[4] = {0.f, 0.f, 0.f, 0.f};
    float s1[4] = {0.f, 0.f, 0.f, 0.f};
    mma16816h(s0, aq, bk0);
    mma16816h(s1, aq, bk1);
    #pragma unroll
    for (int r = 0; r < 4; r++) { s0[r] *= 0.25f; s1[r] *= 0.25f; }

    // softmax rows r = lane>>2 (regs 0,1) and r+8 (regs 2,3); cols across quad
    float m0 = fmaxf(fmaxf(s0[0], s0[1]), fmaxf(s1[0], s1[1]));
    float m1 = fmaxf(fmaxf(s0[2], s0[3]), fmaxf(s1[2], s1[3]));
    m0 = fmaxf(m0, __shfl_xor_sync(0xffffffffu, m0, 1));
    m0 = fmaxf(m0, __shfl_xor_sync(0xffffffffu, m0, 2));
    m1 = fmaxf(m1, __shfl_xor_sync(0xffffffffu, m1, 1));
    m1 = fmaxf(m1, __shfl_xor_sync(0xffffffffu, m1, 2));
    s0[0] = __expf(s0[0] - m0); s0[1] = __expf(s0[1] - m0);
    s1[0] = __expf(s1[0] - m0); s1[1] = __expf(s1[1] - m0);
    s0[2] = __expf(s0[2] - m1); s0[3] = __expf(s0[3] - m1);
    s1[2] = __expf(s1[2] - m1); s1[3] = __expf(s1[3] - m1);
    float e0 = s0[0] + s0[1] + s1[0] + s1[1];
    float e1 = s0[2] + s0[3] + s1[2] + s1[3];
    e0 += __shfl_xor_sync(0xffffffffu, e0, 1);
    e0 += __shfl_xor_sync(0xffffffffu, e0, 2);
    e1 += __shfl_xor_sync(0xffffffffu, e1, 1);
    e1 += __shfl_xor_sync(0xffffffffu, e1, 2);
    float i0 = 1.f / e0, i1 = 1.f / e1;
    s0[0] *= i0; s0[1] *= i0; s1[0] *= i0; s1[1] *= i0;
    s0[2] *= i1; s0[3] *= i1; s1[2] *= i1; s1[3] *= i1;

    // P a-frag (c-frag -> a-frag identity repack)
    uint32_t ap[4];
    ap[0] = pack_h2(s0[0], s0[1]);
    ap[1] = pack_h2(s0[2], s0[3]);
    ap[2] = pack_h2(s1[0], s1[1]);
    ap[3] = pack_h2(s1[2], s1[3]);

    float o0[4] = {0.f, 0.f, 0.f, 0.f};
    float o1[4] = {0.f, 0.f, 0.f, 0.f};
    mma16816h(o0, ap, bv0);
    mma16816h(o1, ap, bv1);

    int r = lane >> 2, c2 = (lane & 3) * 2;
    *(uint32_t*)&g_Cs[bse + r * 16 + c2]           = pack_h2(o0[0], o0[1]);
    *(uint32_t*)&g_Cs[bse + (r + 8) * 16 + c2]     = pack_h2(o0[2], o0[3]);
    *(uint32_t*)&g_Cs[bse + r * 16 + c2 + 8]       = pack_h2(o1[0], o1[1]);
    *(uint32_t*)&g_Cs[bse + (r + 8) * 16 + c2 + 8] = pack_h2(o1[2], o1[3]);
}

// ---------------------------------------------------------------------------
// Fused FFN (R14-proven, unchanged)
// ---------------------------------------------------------------------------
#define FF_CHUNK(ACC) do {                                                   \
    _Pragma("unroll")                                                        \
    for (int k16 = 0; k16 < 2; k16++) {                                      \
        int kbase = k16 * 16 + kk_off;                                       \
        uint32_t bh[4][2];                                                   \
        _Pragma("unroll")                                                    \
        for (int in2 = 0; in2 < 2; in2++) {                                  \
            int nrow = wn * 32 + in2 * 16 + row_off;                         \
            uint32_t t[4];                                                   \
            ldm4(t, stB + sw64((uint32_t)(nrow * 64 + kbase * 2)));          \
            bh[in2 * 2 + 0][0] = t[0]; bh[in2 * 2 + 0][1] = t[2];            \
            bh[in2 * 2 + 1][0] = t[1]; bh[in2 * 2 + 1][1] = t[3];            \
        }                                                                    \
        uint32_t af[4][4];                                                   \
        _Pragma("unroll")                                                    \
        for (int im = 0; im < 4; im++) {                                     \
            int mrow = im * 16 + row_off;                                    \
            ldm4(af[im], stA + sw64((uint32_t)(mrow * 64 + kbase * 2)));     \
        }                                                                    \
        _Pragma("unroll")                                                    \
        for (int im = 0; im < 4; im++)                                       \
            _Pragma("unroll")                                                \
            for (int in = 0; in < 4; in++)                                   \
                mma16816h(ACC[im][in], af[im], bh[in]);                      \
    }                                                                        \
} while (0)

__global__ __launch_bounds__(128, 3) void ffn_fused_kernel(
    int lbase,
    const float* __restrict__ B1, const float* __restrict__ B2,
    const float* __restrict__ gam, const float* __restrict__ bet)
{
    extern __shared__ char dsm[];
    __shared__ float s_sp[64][4];
    __shared__ float s_sq[64][4];

    uint32_t raw_u = smem_u32(dsm);
    uint32_t sbase = (raw_u + 1023) & ~1023u;
    char* dsm_al = dsm + (sbase - raw_u);

    int tid = threadIdx.x;
    int wn = tid >> 5, lane = tid & 31;
    int rb = blockIdx.x * 64;

    int mt = lane >> 3, rr = lane & 7;
    int row_off = ((mt & 1) << 3) + rr;
    int kk_off = (mt >> 1) << 3;
    int r_in = lane >> 2;
    int c_in = (lane & 3) * 2;

    const char* wbase = (const char*)(g_Wt + (size_t)(lbase + 16) * SLOT_ELE);

    const __half* hsrc = g_Hs + (size_t)rb * DIM;
    #pragma unroll
    for (int p = 0; p < 8; p++) {
        int g = p * 128 + tid;
        int kc = g >> 8, r = (g >> 2) & 63, kq = (g & 3) * 8;
        cpa16(sbase + FF_H + kc * 4096 + sw64((uint32_t)(r * 64 + kq * 2)),
              hsrc + (size_t)r * DIM + kc * 32 + kq);
    }
    cp_commit();

    auto issueB = [&](int buf, int c) {
        int j = c >> 3, half = (c >> 2) & 1, kc = c & 3;
        const char* bs = wbase + (size_t)((half ? 32 : 0) + j * 4 + kc) * 8192;
        uint32_t st = sbase + FF_B + buf * FF_STAGE;
        #pragma unroll
        for (int p = 0; p < 4; p++) {
            uint32_t off = (uint32_t)((p * 128 + tid) * 16);
            cpa16(st + off, bs + off);
        }
    };

    issueB(0, 0); cp_commit();
    issueB(1, 1); cp_commit();

    float oacc[4][4][4];
    float g1[4][4][4];
    #pragma unroll
    for (int i = 0; i < 4; i++)
        #pragma unroll
        for (int j2 = 0; j2 < 4; j2++)
            #pragma unroll
            for (int r = 0; r < 4; r++) oacc[i][j2][r] = 0.f;

    for (int c = 0; c < 64; c++) {
        int j = c >> 3, half = (c >> 2) & 1, kc = c & 3;
        if (c + 1 < 64) cp_wait1(); else cp_wait0();
        __syncthreads();
        if (c + 2 < 64) { issueB((c + 2) % 3, c + 2); cp_commit(); }

        uint32_t stB = sbase + FF_B + (c % 3) * FF_STAGE;
        uint32_t stA = sbase + (half ? FF_HJ : FF_H) + kc * 4096;

        if (half == 0) {
            if (kc == 0) {
                #pragma unroll
                for (int i = 0; i < 4; i++)
                    #pragma unroll
                    for (int j2 = 0; j2 < 4; j2++)
                        #pragma unroll
                        for (int r = 0; r < 4; r++) g1[i][j2][r] = 0.f;
            }
            FF_CHUNK(g1);
            if (kc == 3) {
                #pragma unroll
                for (int im = 0; im < 4; im++)
                    #pragma unroll
                    for (int in = 0; in < 4; in++) {
                        int cl = wn * 32 + in * 8 + c_in;
                        float bb0 = B1[j * 128 + cl];
                        float bb1 = B1[j * 128 + cl + 1];
                        float v0 = fmaxf(g1[im][in][0] + bb0, 0.f);
                        float v1 = fmaxf(g1[im][in][1] + bb1, 0.f);
                        float v2 = fmaxf(g1[im][in][2] + bb0, 0.f);
                        float v3 = fmaxf(g1[im][in][3] + bb1, 0.f);
                        int r0 = im * 16 + r_in;
                        int cc = in * 8 + c_in;
                        *(uint32_t*)(dsm_al + FF_HJ + wn * 4096 +
                            sw64((uint32_t)(r0 * 64 + cc * 2))) = pack_h2(v0, v1);
                        *(uint32_t*)(dsm_al + FF_HJ + wn * 4096 +
                            sw64((uint32_t)((r0 + 8) * 64 + cc * 2))) = pack_h2(v2, v3);
                    }
            }
        } else {
            FF_CHUNK(oacc);
        }
        __syncthreads();
    }

    float sv[4][2] = {}, qv[4][2] = {};
    #pragma unroll
    for (int im = 0; im < 4; im++) {
        size_t gr0 = (size_t)(rb + im * 16 + r_in);
        #pragma unroll
        for (int in = 0; in < 4; in++) {
            int cl = wn * 32 + in * 8 + c_in;
            float b0 = B2[cl], b1v = B2[cl + 1];
            float2 rv0 = *(const float2*)(g_Kb + gr0 * DIM + cl);
            float2 rv1 = *(const float2*)(g_Kb + (gr0 + 8) * DIM + cl);
            float v0 = oacc[im][in][0] + b0 + rv0.x;
            float v1 = oacc[im][in][1] + b1v + rv0.y;
            float v2 = oacc[im][in][2] + b0 + rv1.x;
            float v3 = oacc[im][in][3] + b1v + rv1.y;
            oacc[im][in][0] = v0; oacc[im][in][1] = v1;
            oacc[im][in][2] = v2; oacc[im][in][3] = v3;
            sv[im][0] += v0 + v1; qv[im][0] += v0 * v0 + v1 * v1;
            sv[im][1] += v2 + v3; qv[im][1] += v2 * v2 + v3 * v3;
        }
    }
    #pragma unroll
    for (int im = 0; im < 4; im++)
        #pragma unroll
        for (int h2 = 0; h2 < 2; h2++) {
            float s = sv[im][h2], q = qv[im][h2];
            s += __shfl_xor_sync(0xffffffffu, s, 1);
            s += __shfl_xor_sync(0xffffffffu, s, 2);
            q += __shfl_xor_sync(0xffffffffu, q, 1);
            q += __shfl_xor_sync(0xffffffffu, q, 2);
            if ((lane & 3) == 0) {
                int rl = im * 16 + r_in + h2 * 8;
                s_sp[rl][wn] = s;
                s_sq[rl][wn] = q;
            }
        }
    __syncthreads();
    float mn[4][2], rs[4][2];
    #pragma unroll
    for (int im = 0; im < 4; im++)
        #pragma unroll
        for (int h2 = 0; h2 < 2; h2++) {
            int rl = im * 16 + r_in + h2 * 8;
            float s = s_sp[rl][0] + s_sp[rl][1] + s_sp[rl][2] + s_sp[rl][3];
            float q = s_sq[rl][0] + s_sq[rl][1] + s_sq[rl][2] + s_sq[rl][3];
            float m = s * (1.f / 128.f);
            float var = q * (1.f / 128.f) - m * m;
            mn[im][h2] = m;
            rs[im][h2] = rsqrtf(var + EPSV);
        }
    #pragma unroll
    for (int im = 0; im < 4; im++) {
        size_t gr0 = (size_t)(rb + im * 16 + r_in);
        #pragma unroll
        for (int in = 0; in < 4; in++) {
            int cl = wn * 32 + in * 8 + c_in;
            float g0 = gam[cl], g1v = gam[cl + 1];
            float e0 = bet[cl], e1 = bet[cl + 1];
            float o0 = (oacc[im][in][0] - mn[im][0]) * rs[im][0] * g0 + e0;
            float o1 = (oacc[im][in][1] - mn[im][0]) * rs[im][0] * g1v + e1;
            float o2 = (oacc[im][in][2] - mn[im][1]) * rs[im][1] * g0 + e0;
            float o3 = (oacc[im][in][3] - mn[im][1]) * rs[im][1] * g1v + e1;
            *(float2*)(g_X + gr0 * DIM + cl) = make_float2(o0, o1);
            *(float2*)(g_X + (gr0 + 8) * DIM + cl) = make_float2(o2, o3);
            *(uint32_t*)&g_Xs[gr0 * DIM + cl] = pack_h2(o0, o1);
            *(uint32_t*)&g_Xs[(gr0 + 8) * DIM + cl] = pack_h2(o2, o3);
        }
    }
}

// ---------------------------------------------------------------------------
// Head
// ---------------------------------------------------------------------------
__global__ __launch_bounds__(128) void numproj_kernel(
    const float* __restrict__ num, const float* __restrict__ Wn,
    const float* __restrict__ bnum)
{
    __shared__ float sn[NUMF];
    int b = blockIdx.x, t = threadIdx.x;
    if (t < NUMF) sn[t] = num[(size_t)b * NUMF + t];
    __syncthreads();
    float acc = bnum[t];
    #pragma unroll 1
    for (int k = 0; k < NUMF; k++)
        acc = fmaf(sn[k], Wn[k * DIM + t], acc);
    g_Np[(size_t)b * DIM + t] = acc;
}

__global__ __launch_bounds__(256) void bn_partial_kernel() {
    int j = blockIdx.x, t = threadIdx.x;
    int col = t & 127, half = t >> 7;
    float s = 0.f, q = 0.f;
    for (int i = 0; i < 64; i++) {
        float v = g_Np[(size_t)(j * 128 + half * 64 + i) * DIM + col];
        s += v; q += v * v;
    }
    __shared__ float ss[256], sq[256];
    ss[t] = s; sq[t] = q;
    __syncthreads();
    if (half == 0) {
        g_bnp[j * DIM + col]            = ss[t] + ss[t + 128];
        g_bnp[64 * DIM + j * DIM + col] = sq[t] + sq[t + 128];
    }
}

__global__ __launch_bounds__(128) void bn_final_kernel(
    const float* __restrict__ gamma, const float* __restrict__ beta)
{
    int c = threadIdx.x;
    float s = 0.f, q = 0.f;
    for (int j = 0; j < 64; j++) {
        s += g_bnp[j * DIM + c];
        q += g_bnp[64 * DIM + j * DIM + c];
    }
    float mu = s * (1.f / 8192.f);
    float var = q * (1.f / 8192.f) - mu * mu;
    float a = gamma[c] * rsqrtf(var + EPSV);
    g_bns[c] = a;
    g_bns[DIM + c] = beta[c] - mu * a;
}

__global__ __launch_bounds__(256) void final_kernel(
    const float* __restrict__ gcn, const float* __restrict__ Wf,
    const float* __restrict__ bf, float* __restrict__ out)
{
    int b = blockIdx.x, t = threadIdx.x;
    const float* xr = g_X + (size_t)b * (SEQ * DIM);
    float acc = 0.f;
    #pragma unroll
    for (int i = 0; i < 8; i++) {
        int idx = t + 256 * i;
        acc = fmaf(xr[idx], Wf[idx], acc);
    }
    if (t < GCN)
        acc = fmaf(gcn[(size_t)b * GCN + t], Wf[SEQ * DIM + t], acc);
    if (t < DIM) {
        float v = g_Np[(size_t)b * DIM + t] * g_bns[t] + g_bns[DIM + t];
        acc = fmaf(v, Wf[SEQ * DIM + GCN + t], acc);
    }
    acc = warp_red(acc);
    __shared__ float red[8];
    if ((t & 31) == 0) red[t >> 5] = acc;
    __syncthreads();
    if (t == 0) {
        float z = red[0] + red[1] + red[2] + red[3]
                + red[4] + red[5] + red[6] + red[7] + bf[0];
        out[b] = 1.f / (1.f + expf(-z));
    }
}

// ---------------------------------------------------------------------------
// Launch
// ---------------------------------------------------------------------------
extern "C" void kernel_launch(void* const* d_in, const int* in_sizes, int n_in,
                              void* d_out, int out_size)
{
    const float* x    = (const float*)d_in[0];
    const float* gcn  = (const float*)d_in[1];
    const float* num  = (const float*)d_in[2];
    const float* Wq   = (const float*)d_in[3];
    const float* bq   = (const float*)d_in[4];
    const float* Wk   = (const float*)d_in[5];
    const float* bk   = (const float*)d_in[6];
    const float* Wv   = (const float*)d_in[7];
    const float* bv   = (const float*)d_in[8];
    const float* Wo   = (const float*)d_in[9];
    const float* bo   = (const float*)d_in[10];
    const float* ln1g = (const float*)d_in[11];
    const float* ln1b = (const float*)d_in[12];
    const float* W1   = (const float*)d_in[13];
    const float* b1   = (const float*)d_in[14];
    const float* W2   = (const float*)d_in[15];
    const float* b2   = (const float*)d_in[16];
    const float* ln2g = (const float*)d_in[17];
    const float* ln2b = (const float*)d_in[18];
    const float* Wn   = (const float*)d_in[19];
    const float* bnum = (const float*)d_in[20];
    const float* bng  = (const float*)d_in[21];
    const float* bnb  = (const float*)d_in[22];
    const float* Wf   = (const float*)d_in[23];
    const float* bf   = (const float*)d_in[24];
    float* out = (float*)d_out;

    cudaFuncSetAttribute(qkv_fused_kernel,
        cudaFuncAttributeMaxDynamicSharedMemorySize, DSMEM_QKV);
    cudaFuncSetAttribute(wo_ln_kernel,
        cudaFuncAttributeMaxDynamicSharedMemorySize, DSMEM_BYTES);
    cudaFuncSetAttribute(ffn_fused_kernel,
        cudaFuncAttributeMaxDynamicSharedMemorySize, DSMEM_FF);

    pe_init_kernel<<<2, 1024>>>();
    prep_weights_kernel<<<SLOTS_TOTAL, 256>>>(Wq, Wk, Wv, Wo, W1, W2);
    add_pe_kernel<<<16384, 256>>>(x);

    for (int l = 0; l < 2; l++) {
        int lb = l * 80;
        // QKV single-pass: g_Xs -> Qh,Kh,Vh (fp16), A read once
        qkv_fused_kernel<<<MTOT / 128, 256, DSMEM_QKV>>>(
            lb, bq + l * DIM, bk + l * DIM, bv + l * DIM);
        // tensor-core attention: -> ctx fp16 (g_Cs)
        attn_tc_kernel<<<MTOT / 16, 256>>>();
        // h = LN(ctx @ Wo + bo + X): fp32 -> g_Kb, fp16 -> g_Hs
        wo_ln_kernel<<<MTOT / 128, 256, DSMEM_BYTES>>>(
            lb + 12, bo + l * DIM, ln1g + l * DIM, ln1b + l * DIM);
        // fused FFN: out = LN(relu(h@W1+b1)@W2 + b2 + h) -> g_X + g_Xs
        ffn_fused_kernel<<<MTOT / 64, 128, DSMEM_FF>>>(
            lb, b1 + l * HID, b2 + l * DIM,
            ln2g + l * DIM, ln2b + l * DIM);
    }

    numproj_kernel<<<BATCH, 128>>>(num, Wn, bnum);
    bn_partial_kernel<<<64, 256>>>();
    bn_final_kernel<<<1, 128>>>(bng, bnb);
    final_kernel<<<BATCH, 256>>>(gcn, Wf, bf, out);
}

// round 17
// speedup vs baseline: 1.6508x; 1.1780x over previous
#include <cuda_runtime.h>
#include <cuda_fp16.h>
#include <math.h>
#include <stdint.h>

// ---------------------------------------------------------------------------
// Problem constants
// ---------------------------------------------------------------------------
#define BATCH 8192
#define SEQ   16
#define DIM   128
#define MTOT  (BATCH * SEQ)        // 131072 rows
#define HID   1024
#define GCN   40
#define NUMF  103
#define EPSV  1e-5f

// Weight-tile store: each "slot" = one 128(N)x32(K) fp16 tile,
// SW64-swizzled 64B rows — ldmatrix-ready. 4096 fp16 = 8KB.
#define SLOT_ELE    4096
#define SLOTS_TOTAL 160              // 80 per layer x 2 layers
// per-layer map: Wq:0-3 Wk:4-7 Wv:8-11 Wo:12-15 W1:16+nb*4+kc W2:48+kc

// Generic GEMM (Wo): tile 128x128, Kchunk=64 (2 sub-tiles of 32), 8 warps.
#define OA    0u
#define OB    16384u
#define STAGE_B 32768u
#define NSTAGE 3
#define DSMEM_BYTES (1024 + NSTAGE * STAGE_B)   // 99328

// QKV fused: A resident 32KB + B ring 3x16KB
#define QKV_A   0u
#define QKV_B   32768u
#define QKV_STG 16384u
#define DSMEM_QKV (1024 + 32768 + 3 * QKV_STG)  // 82944

// Fused-FFN smem: h 16KB + Hj 16KB + B-ring 3x8KB
#define FF_STAGE 8192u
#define FF_H  0u
#define FF_HJ 16384u
#define FF_B  32768u
#define DSMEM_FF (1024 + 32768 + 3 * FF_STAGE)   // 58368

// ---------------------------------------------------------------------------
// Scratch
// ---------------------------------------------------------------------------
__device__ float g_Np[BATCH * DIM];
__device__ float g_bnp[2 * 64 * DIM];
__device__ float g_bns[2 * DIM];
__device__ float g_PE[SEQ * DIM];
__device__ __half g_Wt[(size_t)SLOTS_TOTAL * SLOT_ELE];
__device__ __half g_Xs[(size_t)MTOT * DIM];   // layer io (fp16)
__device__ __half g_Cs[(size_t)MTOT * DIM];   // ctx -> Wo input
__device__ __half g_Hs[(size_t)MTOT * DIM];   // h -> FFN input + FF residual
__device__ __half g_Qh[(size_t)MTOT * DIM];   // q
__device__ __half g_Kh[(size_t)MTOT * DIM];   // k
__device__ __half g_Vh[(size_t)MTOT * DIM];   // v

__device__ __forceinline__ float warp_red(float v) {
    #pragma unroll
    for (int o = 16; o; o >>= 1) v += __shfl_xor_sync(0xffffffffu, v, o);
    return v;
}

// ---------------------------------------------------------------------------
// PTX helpers
// ---------------------------------------------------------------------------
__device__ __forceinline__ uint32_t smem_u32(const void* p) {
    uint32_t a;
    asm("{ .reg .u64 t; cvta.to.shared.u64 t, %1; cvt.u32.u64 %0, t; }"
        : "=r"(a) : "l"(p));
    return a;
}

__device__ __forceinline__ void ldm4(uint32_t* r, uint32_t addr) {
    asm volatile("ldmatrix.sync.aligned.m8n8.x4.shared.b16 {%0,%1,%2,%3}, [%4];"
                 : "=r"(r[0]), "=r"(r[1]), "=r"(r[2]), "=r"(r[3]) : "r"(addr));
}
__device__ __forceinline__ void ldm2(uint32_t* r, uint32_t addr) {
    asm volatile("ldmatrix.sync.aligned.m8n8.x2.shared.b16 {%0,%1}, [%2];"
                 : "=r"(r[0]), "=r"(r[1]) : "r"(addr));
}
__device__ __forceinline__ void ldm2t(uint32_t* r, uint32_t addr) {
    asm volatile("ldmatrix.sync.aligned.m8n8.x2.trans.shared.b16 {%0,%1}, [%2];"
                 : "=r"(r[0]), "=r"(r[1]) : "r"(addr));
}

__device__ __forceinline__ void mma16816h(float* c, const uint32_t* a,
                                          const uint32_t* b) {
    asm volatile(
        "mma.sync.aligned.m16n8k16.row.col.f32.f16.f16.f32 "
        "{%0,%1,%2,%3}, {%4,%5,%6,%7}, {%8,%9}, {%0,%1,%2,%3};"
        : "+f"(c[0]), "+f"(c[1]), "+f"(c[2]), "+f"(c[3])
        : "r"(a[0]), "r"(a[1]), "r"(a[2]), "r"(a[3]), "r"(b[0]), "r"(b[1]));
}

__device__ __forceinline__ void cpa16(uint32_t dst, const void* src) {
    asm volatile("{ .reg .u64 g; cvta.to.global.u64 g, %1; "
                 "cp.async.cg.shared.global [%0], [g], 16; }"
                 :: "r"(dst), "l"(src));
}
__device__ __forceinline__ void cp_commit() {
    asm volatile("cp.async.commit_group;" ::: "memory");
}
__device__ __forceinline__ void cp_wait0() {
    asm volatile("cp.async.wait_group 0;" ::: "memory");
}
__device__ __forceinline__ void cp_wait1() {
    asm volatile("cp.async.wait_group 1;" ::: "memory");
}

__device__ __forceinline__ uint32_t sw64(uint32_t off) {
    return off ^ ((off >> 3) & 0x30);
}

__device__ __forceinline__ uint32_t pack_h2(float a, float b) {
    uint32_t h;
    asm("cvt.rn.f16x2.f32 %0, %1, %2;" : "=r"(h) : "f"(b), "f"(a));
    return h;
}
__device__ __forceinline__ float2 h2f2(const __half* p) {
    return __half22float2(*(const __half2*)p);
}

// ---------------------------------------------------------------------------
// PE init + add (fp16 plane only)
// ---------------------------------------------------------------------------
__global__ void pe_init_kernel() {
    int idx = blockIdx.x * 1024 + threadIdx.x;
    if (idx < SEQ * DIM) {
        int s = idx >> 7, d = idx & 127;
        double e = (double)((d >> 1) * 2) / (double)DIM;
        double p = (double)s / pow(10000.0, e);
        g_PE[idx] = (float)((d & 1) ? cos(p) : sin(p));
    }
}

__global__ void add_pe_kernel(const float* __restrict__ x) {
    size_t i4 = (size_t)blockIdx.x * 256 + threadIdx.x;
    float4 xv = ((const float4*)x)[i4];
    int sd = (int)((i4 * 4) & 2047);
    float4 pv = *(const float4*)(g_PE + sd);
    xv.x += pv.x; xv.y += pv.y; xv.z += pv.z; xv.w += pv.w;
    *(uint2*)(&g_Xs[i4 * 4]) =
        make_uint2(pack_h2(xv.x, xv.y), pack_h2(xv.z, xv.w));
}

// ---------------------------------------------------------------------------
// Weight prep (unchanged slot format)
// ---------------------------------------------------------------------------
__global__ __launch_bounds__(256) void prep_weights_kernel(
    const float* __restrict__ Wq, const float* __restrict__ Wk,
    const float* __restrict__ Wv, const float* __restrict__ Wo,
    const float* __restrict__ W1, const float* __restrict__ W2)
{
    int slot = blockIdx.x;
    int l = slot / 80, s = slot % 80;
    const float* W; int Nmat, nb, kc;
    if (s < 16) {
        int m = s >> 2; kc = s & 3; nb = 0; Nmat = 128;
        const float* mats[4] = {Wq, Wk, Wv, Wo};
        W = mats[m] + (size_t)l * DIM * DIM;
    } else if (s < 48) {
        int t = s - 16; nb = t >> 2; kc = t & 3; Nmat = HID;
        W = W1 + (size_t)l * DIM * HID;
    } else {
        int t = s - 48; nb = 0; kc = t; Nmat = 128;
        W = W2 + (size_t)l * HID * DIM;
    }
    char* tile = (char*)(g_Wt + (size_t)slot * SLOT_ELE);

    int g = threadIdx.x;
    #pragma unroll
    for (int it = 0; it < 2; it++, g += 256) {
        int n_local = g >> 2;
        int kq = (g & 3) * 8;
        uint4 hi4;
        uint32_t* hp = (uint32_t*)&hi4;
        #pragma unroll
        for (int u = 0; u < 4; u++) {
            float v0 = W[(size_t)(kc * 32 + kq + u * 2 + 0) * Nmat + nb * 128 + n_local];
            float v1 = W[(size_t)(kc * 32 + kq + u * 2 + 1) * Nmat + nb * 128 + n_local];
            hp[u] = pack_h2(v0, v1);
        }
        *(uint4*)(tile + sw64((uint32_t)(n_local * 64 + kq * 2))) = hi4;
    }
}

// ---------------------------------------------------------------------------
// Shared compute helper: one K16 step of the 64x32-warp-tile MMA
// ---------------------------------------------------------------------------
#define K16_STEP(stA_, stB_, kb_, ACC) do {                                  \
    uint32_t bh[4][2];                                                       \
    _Pragma("unroll")                                                        \
    for (int in2 = 0; in2 < 2; in2++) {                                      \
        int nrow = wn * 32 + in2 * 16 + row_off;                             \
        uint32_t t[4];                                                       \
        ldm4(t, (stB_) + sw64((uint32_t)(nrow * 64 + (kb_) * 2)));           \
        bh[in2 * 2 + 0][0] = t[0]; bh[in2 * 2 + 0][1] = t[2];                \
        bh[in2 * 2 + 1][0] = t[1]; bh[in2 * 2 + 1][1] = t[3];                \
    }                                                                        \
    uint32_t af[4][4];                                                       \
    _Pragma("unroll")                                                        \
    for (int im = 0; im < 4; im++) {                                         \
        int mrow = wm * 64 + im * 16 + row_off;                              \
        ldm4(af[im], (stA_) + sw64((uint32_t)(mrow * 64 + (kb_) * 2)));      \
    }                                                                        \
    _Pragma("unroll")                                                        \
    for (int im = 0; im < 4; im++)                                           \
        _Pragma("unroll")                                                    \
        for (int in = 0; in < 4; in++)                                       \
            mma16816h(ACC[im][in], af[im], bh[in]);                          \
} while (0)

// ---------------------------------------------------------------------------
// Wo GEMM + LN (Kchunk=64): h = LN(ctx@Wo + bo + Xs) -> g_Hs (fp16)
// residual read from g_Xs (fp16)
// ---------------------------------------------------------------------------
__global__ __launch_bounds__(256, 2) void wo_ln_kernel(
    int slotbase,
    const float* __restrict__ bias,
    const float* __restrict__ gam, const float* __restrict__ bet)
{
    extern __shared__ char dsm[];
    __shared__ float s_sp[128][4];
    __shared__ float s_sq[128][4];

    uint32_t raw_u = smem_u32(dsm);
    uint32_t sbase = (raw_u + 1023) & ~1023u;

    int tid = threadIdx.x;
    int wid = tid >> 5, lane = tid & 31;
    int wm = wid & 1, wn = wid >> 1;
    int rb = blockIdx.x * 128;

    int mt = lane >> 3, rr = lane & 7;
    int row_off = ((mt & 1) << 3) + rr;
    int kk_off = (mt >> 1) << 3;

    const __half* A = g_Cs;
    const char* bbase = (const char*)(g_Wt + (size_t)slotbase * SLOT_ELE);

    uint32_t ag_dst[4];
    const __half* ag_src[4];
    #pragma unroll
    for (int p = 0; p < 4; p++) {
        int g = p * 256 + tid;
        int sub = g >> 9, idx = g & 511;
        int arow = idx >> 2, kq = (idx & 3) * 8;
        ag_dst[p] = sub * 8192 + sw64((uint32_t)(arow * 64 + kq * 2));
        ag_src[p] = A + (size_t)(rb + arow) * DIM + sub * 32 + kq;
    }

    float acc[4][4][4];
    #pragma unroll
    for (int i = 0; i < 4; i++)
        #pragma unroll
        for (int j = 0; j < 4; j++)
            #pragma unroll
            for (int r = 0; r < 4; r++) acc[i][j][r] = 0.f;

    auto issue = [&](int buf, int c) {
        uint32_t st = sbase + buf * STAGE_B;
        #pragma unroll
        for (int p = 0; p < 4; p++)
            cpa16(st + OA + ag_dst[p], ag_src[p] + c * 64);
        const char* bs = bbase + (size_t)c * 16384;
        #pragma unroll
        for (int p = 0; p < 4; p++) {
            uint32_t off = (uint32_t)((p * 256 + tid) * 16);
            cpa16(st + OB + off, bs + off);
        }
    };

    issue(0, 0); cp_commit();
    issue(1, 1); cp_commit();

    for (int c = 0; c < 2; c++) {
        if (c == 0) cp_wait1(); else cp_wait0();
        __syncthreads();
        uint32_t st = sbase + c * STAGE_B;
        #pragma unroll
        for (int k16 = 0; k16 < 4; k16++) {
            uint32_t so = (uint32_t)(k16 >> 1) * 8192;
            int kb = (k16 & 1) * 16 + kk_off;
            K16_STEP(st + OA + so, st + OB + so, kb, acc);
        }
        __syncthreads();
    }

    // LN epilogue (residual g_Xs fp16)
    int r_in = lane >> 2, c_in = (lane & 3) * 2;
    float sv[4][2] = {}, qv[4][2] = {};
    #pragma unroll
    for (int im = 0; im < 4; im++) {
        size_t gr0 = (size_t)(rb + wm * 64 + im * 16 + r_in);
        #pragma unroll
        for (int in = 0; in < 4; in++) {
            int cl = wn * 32 + in * 8 + c_in;
            float b0 = bias[cl], b1 = bias[cl + 1];
            float2 rv0 = h2f2(&g_Xs[gr0 * DIM + cl]);
            float2 rv1 = h2f2(&g_Xs[(gr0 + 8) * DIM + cl]);
            float v0 = acc[im][in][0] + b0 + rv0.x;
            float v1 = acc[im][in][1] + b1 + rv0.y;
            float v2 = acc[im][in][2] + b0 + rv1.x;
            float v3 = acc[im][in][3] + b1 + rv1.y;
            acc[im][in][0] = v0; acc[im][in][1] = v1;
            acc[im][in][2] = v2; acc[im][in][3] = v3;
            sv[im][0] += v0 + v1; qv[im][0] += v0 * v0 + v1 * v1;
            sv[im][1] += v2 + v3; qv[im][1] += v2 * v2 + v3 * v3;
        }
    }
    #pragma unroll
    for (int im = 0; im < 4; im++)
        #pragma unroll
        for (int h2 = 0; h2 < 2; h2++) {
            float s = sv[im][h2], q = qv[im][h2];
            s += __shfl_xor_sync(0xffffffffu, s, 1);
            s += __shfl_xor_sync(0xffffffffu, s, 2);
            q += __shfl_xor_sync(0xffffffffu, q, 1);
            q += __shfl_xor_sync(0xffffffffu, q, 2);
            if ((lane & 3) == 0) {
                int rl = wm * 64 + im * 16 + r_in + h2 * 8;
                s_sp[rl][wn] = s;
                s_sq[rl][wn] = q;
            }
        }
    __syncthreads();
    float mn[4][2], rs[4][2];
    #pragma unroll
    for (int im = 0; im < 4; im++)
        #pragma unroll
        for (int h2 = 0; h2 < 2; h2++) {
            int rl = wm * 64 + im * 16 + r_in + h2 * 8;
            float s = s_sp[rl][0] + s_sp[rl][1] + s_sp[rl][2] + s_sp[rl][3];
            float q = s_sq[rl][0] + s_sq[rl][1] + s_sq[rl][2] + s_sq[rl][3];
            float m = s * (1.f / 128.f);
            float var = q * (1.f / 128.f) - m * m;
            mn[im][h2] = m;
            rs[im][h2] = rsqrtf(var + EPSV);
        }
    #pragma unroll
    for (int im = 0; im < 4; im++) {
        size_t gr0 = (size_t)(rb + wm * 64 + im * 16 + r_in);
        #pragma unroll
        for (int in = 0; in < 4; in++) {
            int cl = wn * 32 + in * 8 + c_in;
            float g0 = gam[cl], g1 = gam[cl + 1];
            float e0 = bet[cl], e1 = bet[cl + 1];
            float o0 = (acc[im][in][0] - mn[im][0]) * rs[im][0] * g0 + e0;
            float o1 = (acc[im][in][1] - mn[im][0]) * rs[im][0] * g1 + e1;
            float o2 = (acc[im][in][2] - mn[im][1]) * rs[im][1] * g0 + e0;
            float o3 = (acc[im][in][3] - mn[im][1]) * rs[im][1] * g1 + e1;
            *(uint32_t*)&g_Hs[gr0 * DIM + cl] = pack_h2(o0, o1);
            *(uint32_t*)&g_Hs[(gr0 + 8) * DIM + cl] = pack_h2(o2, o3);
        }
    }
}

// ---------------------------------------------------------------------------
// Single-pass QKV: A (g_Xs) resident in smem, loop q/k/v weights.
// ---------------------------------------------------------------------------
__global__ __launch_bounds__(256, 2) void qkv_fused_kernel(
    int lbase, const float* __restrict__ bq,
    const float* __restrict__ bk, const float* __restrict__ bv)
{
    extern __shared__ char dsm[];
    uint32_t raw_u = smem_u32(dsm);
    uint32_t sbase = (raw_u + 1023) & ~1023u;

    int tid = threadIdx.x;
    int wid = tid >> 5, lane = tid & 31;
    int wm = wid & 1, wn = wid >> 1;
    int rb = blockIdx.x * 128;

    int mt = lane >> 3, rr = lane & 7;
    int row_off = ((mt & 1) << 3) + rr;
    int kk_off = (mt >> 1) << 3;
    int r_in = lane >> 2, c_in = (lane & 3) * 2;

    const char* wbase = (const char*)(g_Wt + (size_t)lbase * SLOT_ELE);

    {
        const __half* asrc = g_Xs + (size_t)rb * DIM;
        #pragma unroll
        for (int p = 0; p < 8; p++) {
            int g = p * 256 + tid;
            int st = g >> 9, idx = g & 511;
            int arow = idx >> 2, kq = (idx & 3) * 8;
            cpa16(sbase + QKV_A + st * 8192 + sw64((uint32_t)(arow * 64 + kq * 2)),
                  asrc + (size_t)arow * DIM + st * 32 + kq);
        }
    }
    auto issueB = [&](int buf, int c) {
        const char* bs = wbase + (size_t)c * 16384;
        uint32_t st = sbase + QKV_B + buf * QKV_STG;
        #pragma unroll
        for (int p = 0; p < 4; p++) {
            uint32_t off = (uint32_t)((p * 256 + tid) * 16);
            cpa16(st + off, bs + off);
        }
    };
    issueB(0, 0); cp_commit();
    issueB(1, 1); cp_commit();

    float acc[4][4][4];
    #pragma unroll
    for (int i = 0; i < 4; i++)
        #pragma unroll
        for (int j = 0; j < 4; j++)
            #pragma unroll
            for (int r = 0; r < 4; r++) acc[i][j][r] = 0.f;

    for (int c = 0; c < 6; c++) {
        int w = c >> 1, part = c & 1;
        if (c + 1 < 6) cp_wait1(); else cp_wait0();
        __syncthreads();
        if (c + 2 < 6) { issueB((c + 2) % 3, c + 2); cp_commit(); }

        uint32_t stB = sbase + QKV_B + (c % 3) * QKV_STG;
        uint32_t stA = sbase + QKV_A + part * 16384;
        #pragma unroll
        for (int k16 = 0; k16 < 4; k16++) {
            uint32_t so = (uint32_t)(k16 >> 1) * 8192;
            int kb = (k16 & 1) * 16 + kk_off;
            K16_STEP(stA + so, stB + so, kb, acc);
        }

        if (part == 1) {
            __half* Sh = (w == 0) ? g_Qh : (w == 1) ? g_Kh : g_Vh;
            const float* bias = (w == 0) ? bq : (w == 1) ? bk : bv;
            #pragma unroll
            for (int im = 0; im < 4; im++) {
                size_t gr0 = (size_t)(rb + wm * 64 + im * 16 + r_in);
                #pragma unroll
                for (int in = 0; in < 4; in++) {
                    int cl = wn * 32 + in * 8 + c_in;
                    float b0 = bias[cl], b1 = bias[cl + 1];
                    *(uint32_t*)&Sh[gr0 * DIM + cl] =
                        pack_h2(acc[im][in][0] + b0, acc[im][in][1] + b1);
                    *(uint32_t*)&Sh[(gr0 + 8) * DIM + cl] =
                        pack_h2(acc[im][in][2] + b0, acc[im][in][3] + b1);
                    #pragma unroll
                    for (int r = 0; r < 4; r++) acc[im][in][r] = 0.f;
                }
            }
        }
        __syncthreads();
    }
}

// ---------------------------------------------------------------------------
// Tensor-core attention (R15-proven)
// ---------------------------------------------------------------------------
__global__ __launch_bounds__(256) void attn_tc_kernel() {
    __shared__ __align__(16) char sm[8 * 2304];

    int w = threadIdx.x >> 5, lane = threadIdx.x & 31;
    size_t n = (size_t)blockIdx.x * 8 + w;
    size_t bse = n * 256;
    char* tb = sm + w * 2304;
    uint32_t qb = smem_u32(tb);

    {
        int row = lane >> 1, half = lane & 1;
        uint32_t doff = (uint32_t)(row * 48 + half * 16);
        size_t soff = bse + row * 16 + half * 8;
        *(uint4*)(tb + doff)        = *(const uint4*)(g_Qh + soff);
        *(uint4*)(tb + 768 + doff)  = *(const uint4*)(g_Kh + soff);
        *(uint4*)(tb + 1536 + doff) = *(const uint4*)(g_Vh + soff);
    }
    __syncwarp();

    uint32_t aq[4];
    ldm4(aq, qb + (lane & 15) * 48 + (lane >> 4) * 16);
    uint32_t bk0[2], bk1[2];
    {
        uint32_t addr = qb + 768 + (lane & 7) * 48 + ((lane >> 3) & 1) * 16;
        ldm2(bk0, addr);
        ldm2(bk1, addr + 8 * 48);
    }
    uint32_t bv0[2], bv1[2];
    {
        uint32_t addr = qb + 1536 + (lane & 15) * 48;
        ldm2t(bv0, addr);
        ldm2t(bv1, addr + 16);
    }

    float s0[4] = {0.f, 0.f, 0.f, 0.f};
    float s1[4] = {0.f, 0.f, 0.f, 0.f};
    mma16816h(s0, aq, bk0);
    mma16816h(s1, aq, bk1);
    #pragma unroll
    for (int r = 0; r < 4; r++) { s0[r] *= 0.25f; s1[r] *= 0.25f; }

    float m0 = fmaxf(fmaxf(s0[0], s0[1]), fmaxf(s1[0], s1[1]));
    float m1 = fmaxf(fmaxf(s0[2], s0[3]), fmaxf(s1[2], s1[3]));
    m0 = fmaxf(m0, __shfl_xor_sync(0xffffffffu, m0, 1));
    m0 = fmaxf(m0, __shfl_xor_sync(0xffffffffu, m0, 2));
    m1 = fmaxf(m1, __shfl_xor_sync(0xffffffffu, m1, 1));
    m1 = fmaxf(m1, __shfl_xor_sync(0xffffffffu, m1, 2));
    s0[0] = __expf(s0[0] - m0); s0[1] = __expf(s0[1] - m0);
    s1[0] = __expf(s1[0] - m0); s1[1] = __expf(s1[1] - m0);
    s0[2] = __expf(s0[2] - m1); s0[3] = __expf(s0[3] - m1);
    s1[2] = __expf(s1[2] - m1); s1[3] = __expf(s1[3] - m1);
    float e0 = s0[0] + s0[1] + s1[0] + s1[1];
    float e1 = s0[2] + s0[3] + s1[2] + s1[3];
    e0 += __shfl_xor_sync(0xffffffffu, e0, 1);
    e0 += __shfl_xor_sync(0xffffffffu, e0, 2);
    e1 += __shfl_xor_sync(0xffffffffu, e1, 1);
    e1 += __shfl_xor_sync(0xffffffffu, e1, 2);
    float i0 = 1.f / e0, i1 = 1.f / e1;
    s0[0] *= i0; s0[1] *= i0; s1[0] *= i0; s1[1] *= i0;
    s0[2] *= i1; s0[3] *= i1; s1[2] *= i1; s1[3] *= i1;

    uint32_t ap[4];
    ap[0] = pack_h2(s0[0], s0[1]);
    ap[1] = pack_h2(s0[2], s0[3]);
    ap[2] = pack_h2(s1[0], s1[1]);
    ap[3] = pack_h2(s1[2], s1[3]);

    float o0[4] = {0.f, 0.f, 0.f, 0.f};
    float o1[4] = {0.f, 0.f, 0.f, 0.f};
    mma16816h(o0, ap, bv0);
    mma16816h(o1, ap, bv1);

    int r = lane >> 2, c2 = (lane & 3) * 2;
    *(uint32_t*)&g_Cs[bse + r * 16 + c2]           = pack_h2(o0[0], o0[1]);
    *(uint32_t*)&g_Cs[bse + (r + 8) * 16 + c2]     = pack_h2(o0[2], o0[3]);
    *(uint32_t*)&g_Cs[bse + r * 16 + c2 + 8]       = pack_h2(o1[0], o1[1]);
    *(uint32_t*)&g_Cs[bse + (r + 8) * 16 + c2 + 8] = pack_h2(o1[2], o1[3]);
}

// ---------------------------------------------------------------------------
// Fused FFN: out = LN(relu(h@W1+b1)@W2 + b2 + h) -> g_Xs only.
// Residual h read from the resident smem FF_H tile (no gmem round-trip).
// ---------------------------------------------------------------------------
#define FF_CHUNK(ACC) do {                                                   \
    _Pragma("unroll")                                                        \
    for (int k16 = 0; k16 < 2; k16++) {                                      \
        int kbase = k16 * 16 + kk_off;                                       \
        uint32_t bh[4][2];                                                   \
        _Pragma("unroll")                                                    \
        for (int in2 = 0; in2 < 2; in2++) {                                  \
            int nrow = wn * 32 + in2 * 16 + row_off;                         \
            uint32_t t[4];                                                   \
            ldm4(t, stB + sw64((uint32_t)(nrow * 64 + kbase * 2)));          \
            bh[in2 * 2 + 0][0] = t[0]; bh[in2 * 2 + 0][1] = t[2];            \
            bh[in2 * 2 + 1][0] = t[1]; bh[in2 * 2 + 1][1] = t[3];            \
        }                                                                    \
        uint32_t af[4][4];                                                   \
        _Pragma("unroll")                                                    \
        for (int im = 0; im < 4; im++) {                                     \
            int mrow = im * 16 + row_off;                                    \
            ldm4(af[im], stA + sw64((uint32_t)(mrow * 64 + kbase * 2)));     \
        }                                                                    \
        _Pragma("unroll")                                                    \
        for (int im = 0; im < 4; im++)                                       \
            _Pragma("unroll")                                                \
            for (int in = 0; in < 4; in++)                                   \
                mma16816h(ACC[im][in], af[im], bh[in]);                      \
    }                                                                        \
} while (0)

__global__ __launch_bounds__(128, 3) void ffn_fused_kernel(
    int lbase,
    const float* __restrict__ B1, const float* __restrict__ B2,
    const float* __restrict__ gam, const float* __restrict__ bet)
{
    extern __shared__ char dsm[];
    __shared__ float s_sp[64][4];
    __shared__ float s_sq[64][4];

    uint32_t raw_u = smem_u32(dsm);
    uint32_t sbase = (raw_u + 1023) & ~1023u;
    char* dsm_al = dsm + (sbase - raw_u);

    int tid = threadIdx.x;
    int wn = tid >> 5, lane = tid & 31;
    int rb = blockIdx.x * 64;

    int mt = lane >> 3, rr = lane & 7;
    int row_off = ((mt & 1) << 3) + rr;
    int kk_off = (mt >> 1) << 3;
    int r_in = lane >> 2;
    int c_in = (lane & 3) * 2;

    const char* wbase = (const char*)(g_Wt + (size_t)(lbase + 16) * SLOT_ELE);

    const __half* hsrc = g_Hs + (size_t)rb * DIM;
    #pragma unroll
    for (int p = 0; p < 8; p++) {
        int g = p * 128 + tid;
        int kc = g >> 8, r = (g >> 2) & 63, kq = (g & 3) * 8;
        cpa16(sbase + FF_H + kc * 4096 + sw64((uint32_t)(r * 64 + kq * 2)),
              hsrc + (size_t)r * DIM + kc * 32 + kq);
    }
    cp_commit();

    auto issueB = [&](int buf, int c) {
        int j = c >> 3, half = (c >> 2) & 1, kc = c & 3;
        const char* bs = wbase + (size_t)((half ? 32 : 0) + j * 4 + kc) * 8192;
        uint32_t st = sbase + FF_B + buf * FF_STAGE;
        #pragma unroll
        for (int p = 0; p < 4; p++) {
            uint32_t off = (uint32_t)((p * 128 + tid) * 16);
            cpa16(st + off, bs + off);
        }
    };

    issueB(0, 0); cp_commit();
    issueB(1, 1); cp_commit();

    float oacc[4][4][4];
    float g1[4][4][4];
    #pragma unroll
    for (int i = 0; i < 4; i++)
        #pragma unroll
        for (int j2 = 0; j2 < 4; j2++)
            #pragma unroll
            for (int r = 0; r < 4; r++) oacc[i][j2][r] = 0.f;

    for (int c = 0; c < 64; c++) {
        int j = c >> 3, half = (c >> 2) & 1, kc = c & 3;
        if (c + 1 < 64) cp_wait1(); else cp_wait0();
        __syncthreads();
        if (c + 2 < 64) { issueB((c + 2) % 3, c + 2); cp_commit(); }

        uint32_t stB = sbase + FF_B + (c % 3) * FF_STAGE;
        uint32_t stA = sbase + (half ? FF_HJ : FF_H) + kc * 4096;

        if (half == 0) {
            if (kc == 0) {
                #pragma unroll
                for (int i = 0; i < 4; i++)
                    #pragma unroll
                    for (int j2 = 0; j2 < 4; j2++)
                        #pragma unroll
                        for (int r = 0; r < 4; r++) g1[i][j2][r] = 0.f;
            }
            FF_CHUNK(g1);
            if (kc == 3) {
                #pragma unroll
                for (int im = 0; im < 4; im++)
                    #pragma unroll
                    for (int in = 0; in < 4; in++) {
                        int cl = wn * 32 + in * 8 + c_in;
                        float bb0 = B1[j * 128 + cl];
                        float bb1 = B1[j * 128 + cl + 1];
                        float v0 = fmaxf(g1[im][in][0] + bb0, 0.f);
                        float v1 = fmaxf(g1[im][in][1] + bb1, 0.f);
                        float v2 = fmaxf(g1[im][in][2] + bb0, 0.f);
                        float v3 = fmaxf(g1[im][in][3] + bb1, 0.f);
                        int r0 = im * 16 + r_in;
                        int cc = in * 8 + c_in;
                        *(uint32_t*)(dsm_al + FF_HJ + wn * 4096 +
                            sw64((uint32_t)(r0 * 64 + cc * 2))) = pack_h2(v0, v1);
                        *(uint32_t*)(dsm_al + FF_HJ + wn * 4096 +
                            sw64((uint32_t)((r0 + 8) * 64 + cc * 2))) = pack_h2(v2, v3);
                    }
            }
        } else {
            FF_CHUNK(oacc);
        }
        __syncthreads();
    }

    // LN epilogue: residual h read from resident smem FF_H (fp16)
    float sv[4][2] = {}, qv[4][2] = {};
    #pragma unroll
    for (int im = 0; im < 4; im++) {
        #pragma unroll
        for (int in = 0; in < 4; in++) {
            int cl = wn * 32 + in * 8 + c_in;
            int kcid = cl >> 5, kin = cl & 31;
            int r0 = im * 16 + r_in;
            float b0 = B2[cl], b1v = B2[cl + 1];
            float2 rv0 = h2f2((const __half*)(dsm_al + FF_H + kcid * 4096 +
                               sw64((uint32_t)(r0 * 64 + kin * 2))));
            float2 rv1 = h2f2((const __half*)(dsm_al + FF_H + kcid * 4096 +
                               sw64((uint32_t)((r0 + 8) * 64 + kin * 2))));
            float v0 = oacc[im][in][0] + b0 + rv0.x;
            float v1 = oacc[im][in][1] + b1v + rv0.y;
            float v2 = oacc[im][in][2] + b0 + rv1.x;
            float v3 = oacc[im][in][3] + b1v + rv1.y;
            oacc[im][in][0] = v0; oacc[im][in][1] = v1;
            oacc[im][in][2] = v2; oacc[im][in][3] = v3;
            sv[im][0] += v0 + v1; qv[im][0] += v0 * v0 + v1 * v1;
            sv[im][1] += v2 + v3; qv[im][1] += v2 * v2 + v3 * v3;
        }
    }
    #pragma unroll
    for (int im = 0; im < 4; im++)
        #pragma unroll
        for (int h2 = 0; h2 < 2; h2++) {
            float s = sv[im][h2], q = qv[im][h2];
            s += __shfl_xor_sync(0xffffffffu, s, 1);
            s += __shfl_xor_sync(0xffffffffu, s, 2);
            q += __shfl_xor_sync(0xffffffffu, q, 1);
            q += __shfl_xor_sync(0xffffffffu, q, 2);
            if ((lane & 3) == 0) {
                int rl = im * 16 + r_in + h2 * 8;
                s_sp[rl][wn] = s;
                s_sq[rl][wn] = q;
            }
        }
    __syncthreads();
    float mn[4][2], rs[4][2];
    #pragma unroll
    for (int im = 0; im < 4; im++)
        #pragma unroll
        for (int h2 = 0; h2 < 2; h2++) {
            int rl = im * 16 + r_in + h2 * 8;
            float s = s_sp[rl][0] + s_sp[rl][1] + s_sp[rl][2] + s_sp[rl][3];
            float q = s_sq[rl][0] + s_sq[rl][1] + s_sq[rl][2] + s_sq[rl][3];
            float m = s * (1.f / 128.f);
            float var = q * (1.f / 128.f) - m * m;
            mn[im][h2] = m;
            rs[im][h2] = rsqrtf(var + EPSV);
        }
    #pragma unroll
    for (int im = 0; im < 4; im++) {
        size_t gr0 = (size_t)(rb + im * 16 + r_in);
        #pragma unroll
        for (int in = 0; in < 4; in++) {
            int cl = wn * 32 + in * 8 + c_in;
            float g0 = gam[cl], g1v = gam[cl + 1];
            float e0 = bet[cl], e1 = bet[cl + 1];
            float o0 = (oacc[im][in][0] - mn[im][0]) * rs[im][0] * g0 + e0;
            float o1 = (oacc[im][in][1] - mn[im][0]) * rs[im][0] * g1v + e1;
            float o2 = (oacc[im][in][2] - mn[im][1]) * rs[im][1] * g0 + e0;
            float o3 = (oacc[im][in][3] - mn[im][1]) * rs[im][1] * g1v + e1;
            *(uint32_t*)&g_Xs[gr0 * DIM + cl] = pack_h2(o0, o1);
            *(uint32_t*)&g_Xs[(gr0 + 8) * DIM + cl] = pack_h2(o2, o3);
        }
    }
}

// ---------------------------------------------------------------------------
// Head
// ---------------------------------------------------------------------------
__global__ __launch_bounds__(128) void numproj_kernel(
    const float* __restrict__ num, const float* __restrict__ Wn,
    const float* __restrict__ bnum)
{
    __shared__ float sn[NUMF];
    int b = blockIdx.x, t = threadIdx.x;
    if (t < NUMF) sn[t] = num[(size_t)b * NUMF + t];
    __syncthreads();
    float acc = bnum[t];
    #pragma unroll 1
    for (int k = 0; k < NUMF; k++)
        acc = fmaf(sn[k], Wn[k * DIM + t], acc);
    g_Np[(size_t)b * DIM + t] = acc;
}

__global__ __launch_bounds__(256) void bn_partial_kernel() {
    int j = blockIdx.x, t = threadIdx.x;
    int col = t & 127, half = t >> 7;
    float s = 0.f, q = 0.f;
    for (int i = 0; i < 64; i++) {
        float v = g_Np[(size_t)(j * 128 + half * 64 + i) * DIM + col];
        s += v; q += v * v;
    }
    __shared__ float ss[256], sq[256];
    ss[t] = s; sq[t] = q;
    __syncthreads();
    if (half == 0) {
        g_bnp[j * DIM + col]            = ss[t] + ss[t + 128];
        g_bnp[64 * DIM + j * DIM + col] = sq[t] + sq[t + 128];
    }
}

__global__ __launch_bounds__(128) void bn_final_kernel(
    const float* __restrict__ gamma, const float* __restrict__ beta)
{
    int c = threadIdx.x;
    float s = 0.f, q = 0.f;
    for (int j = 0; j < 64; j++) {
        s += g_bnp[j * DIM + c];
        q += g_bnp[64 * DIM + j * DIM + c];
    }
    float mu = s * (1.f / 8192.f);
    float var = q * (1.f / 8192.f) - mu * mu;
    float a = gamma[c] * rsqrtf(var + EPSV);
    g_bns[c] = a;
    g_bns[DIM + c] = beta[c] - mu * a;
}

__global__ __launch_bounds__(256) void final_kernel(
    const float* __restrict__ gcn, const float* __restrict__ Wf,
    const float* __restrict__ bf, float* __restrict__ out)
{
    int b = blockIdx.x, t = threadIdx.x;
    const __half2* xr = (const __half2*)(g_Xs + (size_t)b * (SEQ * DIM));
    float acc = 0.f;
    #pragma unroll
    for (int i = 0; i < 4; i++) {
        int j = t + 256 * i;               // half2 index 0..1023
        float2 xv = __half22float2(xr[j]);
        float2 wv = ((const float2*)Wf)[j];
        acc = fmaf(xv.x, wv.x, acc);
        acc = fmaf(xv.y, wv.y, acc);
    }
    if (t < GCN)
        acc = fmaf(gcn[(size_t)b * GCN + t], Wf[SEQ * DIM + t], acc);
    if (t < DIM) {
        float v = g_Np[(size_t)b * DIM + t] * g_bns[t] + g_bns[DIM + t];
        acc = fmaf(v, Wf[SEQ * DIM + GCN + t], acc);
    }
    acc = warp_red(acc);
    __shared__ float red[8];
    if ((t & 31) == 0) red[t >> 5] = acc;
    __syncthreads();
    if (t == 0) {
        float z = red[0] + red[1] + red[2] + red[3]
                + red[4] + red[5] + red[6] + red[7] + bf[0];
        out[b] = 1.f / (1.f + expf(-z));
    }
}

// ---------------------------------------------------------------------------
// Launch
// ---------------------------------------------------------------------------
extern "C" void kernel_launch(void* const* d_in, const int* in_sizes, int n_in,
                              void* d_out, int out_size)
{
    const float* x    = (const float*)d_in[0];
    const float* gcn  = (const float*)d_in[1];
    const float* num  = (const float*)d_in[2];
    const float* Wq   = (const float*)d_in[3];
    const float* bq   = (const float*)d_in[4];
    const float* Wk   = (const float*)d_in[5];
    const float* bk   = (const float*)d_in[6];
    const float* Wv   = (const float*)d_in[7];
    const float* bv   = (const float*)d_in[8];
    const float* Wo   = (const float*)d_in[9];
    const float* bo   = (const float*)d_in[10];
    const float* ln1g = (const float*)d_in[11];
    const float* ln1b = (const float*)d_in[12];
    const float* W1   = (const float*)d_in[13];
    const float* b1   = (const float*)d_in[14];
    const float* W2   = (const float*)d_in[15];
    const float* b2   = (const float*)d_in[16];
    const float* ln2g = (const float*)d_in[17];
    const float* ln2b = (const float*)d_in[18];
    const float* Wn   = (const float*)d_in[19];
    const float* bnum = (const float*)d_in[20];
    const float* bng  = (const float*)d_in[21];
    const float* bnb  = (const float*)d_in[22];
    const float* Wf   = (const float*)d_in[23];
    const float* bf   = (const float*)d_in[24];
    float* out = (float*)d_out;

    cudaFuncSetAttribute(qkv_fused_kernel,
        cudaFuncAttributeMaxDynamicSharedMemorySize, DSMEM_QKV);
    cudaFuncSetAttribute(wo_ln_kernel,
        cudaFuncAttributeMaxDynamicSharedMemorySize, DSMEM_BYTES);
    cudaFuncSetAttribute(ffn_fused_kernel,
        cudaFuncAttributeMaxDynamicSharedMemorySize, DSMEM_FF);

    pe_init_kernel<<<2, 1024>>>();
    prep_weights_kernel<<<SLOTS_TOTAL, 256>>>(Wq, Wk, Wv, Wo, W1, W2);
    add_pe_kernel<<<16384, 256>>>(x);

    for (int l = 0; l < 2; l++) {
        int lb = l * 80;
        // QKV single-pass: g_Xs -> Qh,Kh,Vh (fp16)
        qkv_fused_kernel<<<MTOT / 128, 256, DSMEM_QKV>>>(
            lb, bq + l * DIM, bk + l * DIM, bv + l * DIM);
        // tensor-core attention -> ctx fp16 (g_Cs)
        attn_tc_kernel<<<MTOT / 16, 256>>>();
        // h = LN(ctx @ Wo + bo + Xs) -> g_Hs (fp16 only)
        wo_ln_kernel<<<MTOT / 128, 256, DSMEM_BYTES>>>(
            lb + 12, bo + l * DIM, ln1g + l * DIM, ln1b + l * DIM);
        // fused FFN: out = LN(relu(h@W1+b1)@W2 + b2 + h) -> g_Xs only
        ffn_fused_kernel<<<MTOT / 64, 128, DSMEM_FF>>>(
            lb, b1 + l * HID, b2 + l * DIM,
            ln2g + l * DIM, ln2b + l * DIM);
    }

    numproj_kernel<<<BATCH, 128>>>(num, Wn, bnum);
    bn_partial_kernel<<<64, 256>>>();
    bn_final_kernel<<<1, 128>>>(bng, bnb);
    final_kernel<<<BATCH, 256>>>(gcn, Wf, bf, out);
}